// round 13
// baseline (speedup 1.0000x reference)
#include <cuda_runtime.h>
#include <math.h>

#define N_NODES 50000
#define NUM_E   400000
#define ETOT    (NUM_E + N_NODES)   // 450000, self-loops appended
#define IN_C    128
#define HID     32
#define HEADS   8
#define F1      (HEADS * HID)       // 256
#define OUT_C   64
#define K_CL    16
#define NEG_SLOPE 0.2f
#define EPS_F   1e-16f

// ---------------- scratch (device globals; no runtime allocation) -----------
__device__ float g_h1[(size_t)N_NODES * F1];     // x@W1
__device__ float g_out1[(size_t)N_NODES * F1];   // layer1 output (incl. b1)
__device__ float g_h2[(size_t)N_NODES * OUT_C];  // ELU(out1)@W2
__device__ float g_asrc1[N_NODES * HEADS];
__device__ float g_adst1[N_NODES * HEADS];
__device__ float g_asrc2[N_NODES];
__device__ float g_adst2[N_NODES];
// CSR by destination
__device__ int g_deg[N_NODES];
__device__ int g_start[N_NODES + 1];
__device__ int g_cursor[N_NODES];
__device__ int g_csr_src[ETOT];
__device__ int g_bsum[256];
// pre-split weights (packed bf16x2 along k-pairs): [K/2][N]
__device__ unsigned g_w1hi[(IN_C / 2) * F1];
__device__ unsigned g_w1lo[(IN_C / 2) * F1];
__device__ unsigned g_w2hi[(F1 / 2) * OUT_C];
__device__ unsigned g_w2lo[(F1 / 2) * OUT_C];

// ---------------- helpers ----------------------------------------------------
__device__ __forceinline__ float lrelu(float x) { return x > 0.f ? x : NEG_SLOPE * x; }
__device__ __forceinline__ float elu1(float x)  { return x > 0.f ? x : expm1f(x); }

__device__ __forceinline__ unsigned pack_bf16(float f_even, float f_odd) {
    unsigned r;
    asm("cvt.rn.satfinite.bf16x2.f32 %0, %1, %2;" : "=r"(r) : "f"(f_odd), "f"(f_even));
    return r;
}
__device__ __forceinline__ void bf16_split(float f0, float f1, unsigned& hi, unsigned& lo) {
    hi = pack_bf16(f0, f1);
    float b0 = __uint_as_float(hi << 16);
    float b1 = __uint_as_float(hi & 0xffff0000u);
    lo = pack_bf16(f0 - b0, f1 - b1);
}

#define MMA_BF16(d, a, b0_, b1_) \
    asm("mma.sync.aligned.m16n8k16.row.col.f32.bf16.bf16.f32 " \
        "{%0,%1,%2,%3}, {%4,%5,%6,%7}, {%8,%9}, {%0,%1,%2,%3};" \
        : "+f"(d[0]), "+f"(d[1]), "+f"(d[2]), "+f"(d[3]) \
        : "r"(a[0]), "r"(a[1]), "r"(a[2]), "r"(a[3]), "r"(b0_), "r"(b1_))

// ---------------- prep: zero degree hist + split both weight matrices --------
__global__ void prep_kernel(const float* __restrict__ W1, const float* __restrict__ W2) {
    int b = blockIdx.x, tid = threadIdx.x;
    if (b < 196) {
        int i = b * 256 + tid;
        if (i < N_NODES) g_deg[i] = 0;
    } else if (b < 196 + 64) {               // W1: (IN_C/2)*F1 = 16384 = 64*256
        int i = (b - 196) * 256 + tid;
        int kp = i >> 8, n = i & 255;
        unsigned h, l;
        bf16_split(W1[(size_t)(2 * kp) * F1 + n], W1[(size_t)(2 * kp + 1) * F1 + n], h, l);
        g_w1hi[i] = h; g_w1lo[i] = l;
    } else {                                  // W2: (F1/2)*OUT_C = 8192 = 32*256
        int i = (b - 260) * 256 + tid;
        int kp = i >> 6, n = i & 63;
        unsigned h, l;
        bf16_split(W2[(size_t)(2 * kp) * OUT_C + n], W2[(size_t)(2 * kp + 1) * OUT_C + n], h, l);
        g_w2hi[i] = h; g_w2lo[i] = l;
    }
}

// ---------------- edge histogram ---------------------------------------------
__global__ void hist_kernel(const int* __restrict__ ei) {
    int e = blockIdx.x * blockDim.x + threadIdx.x;
    if (e >= ETOT) return;
    int d = (e < NUM_E) ? ei[NUM_E + e] : e - NUM_E;
    atomicAdd(&g_deg[d], 1);
}

// ---------------- CSR: 3-kernel scan + scatter --------------------------------
__global__ void scan1_kernel() {
    __shared__ int sm[256];
    int tid = threadIdx.x;
    int i = blockIdx.x * 256 + tid;
    int v = (i < N_NODES) ? g_deg[i] : 0;
    sm[tid] = v;
    __syncthreads();
    #pragma unroll
    for (int off = 1; off < 256; off <<= 1) {
        int t = (tid >= off) ? sm[tid - off] : 0;
        __syncthreads();
        sm[tid] += t;
        __syncthreads();
    }
    if (i < N_NODES) g_start[i] = sm[tid] - v;   // exclusive
    if (tid == 255) g_bsum[blockIdx.x] = sm[255];
}
__global__ void scan2_kernel(int nblocks) {
    __shared__ int sm[256];
    int tid = threadIdx.x;
    int v = (tid < nblocks) ? g_bsum[tid] : 0;
    sm[tid] = v;
    __syncthreads();
    #pragma unroll
    for (int off = 1; off < 256; off <<= 1) {
        int t = (tid >= off) ? sm[tid - off] : 0;
        __syncthreads();
        sm[tid] += t;
        __syncthreads();
    }
    if (tid < nblocks) g_bsum[tid] = sm[tid] - v;  // exclusive
}
__global__ void scan3_kernel() {
    int tid = threadIdx.x;
    int i = blockIdx.x * 256 + tid;
    if (i < N_NODES) {
        int s = g_start[i] + g_bsum[blockIdx.x];
        g_start[i] = s;
        g_cursor[i] = s;
    }
    if (i == 0) g_start[N_NODES] = ETOT;
}
__global__ void scatter_kernel(const int* __restrict__ ei) {
    int e = blockIdx.x * blockDim.x + threadIdx.x;
    if (e >= ETOT) return;
    int s, d;
    if (e < NUM_E) { s = ei[e]; d = ei[NUM_E + e]; } else { s = d = e - NUM_E; }
    int pos = atomicAdd(&g_cursor[d], 1);
    g_csr_src[pos] = s;
}

// ---------------- bf16 3-product tensor-core GEMM ----------------------------
#define AS_STRIDE 20
template<int BN, bool ELU_A>
__global__ __launch_bounds__(256, 2) void gemm_bf16x3(
    const float* __restrict__ A,
    const unsigned* __restrict__ Bhi, const unsigned* __restrict__ Blo,
    float* __restrict__ C, int M, int Nc, int Kc)
{
    constexpr int NATOM = BN / 16;
    constexpr int BS_STRIDE = BN + 8;
    __shared__ unsigned sAhi[128 * AS_STRIDE];
    __shared__ unsigned sAlo[128 * AS_STRIDE];
    __shared__ unsigned sBhi[16 * BS_STRIDE];
    __shared__ unsigned sBlo[16 * BS_STRIDE];

    const int tid = threadIdx.x;
    const int warp = tid >> 5, lane = tid & 31;
    const int g = lane >> 2, tig = lane & 3;
    const int rowA = blockIdx.y * 128, colB = blockIdx.x * BN;
    const int wm = (warp >> 1) * 32, wn = (warp & 1) * (BN / 2);

    float d[2][NATOM][4];
    #pragma unroll
    for (int i = 0; i < 2; i++)
        #pragma unroll
        for (int j = 0; j < NATOM; j++)
            #pragma unroll
            for (int q = 0; q < 4; q++) d[i][j][q] = 0.f;

    const int arow = tid >> 1;
    const int ak0  = (tid & 1) * 16;
    const bool arow_ok = (rowA + arow) < M;
    const float* Aptr = A + (size_t)(rowA + arow) * Kc + ak0;

    const int bkp = tid >> 4;
    const int bn0 = (tid & 15) * (BN / 16);

    const int KT = Kc / 32;
    for (int kt = 0; kt < KT; kt++) {
        {
            float4 f[4];
            #pragma unroll
            for (int q = 0; q < 4; q++)
                f[q] = arow_ok ? *(const float4*)(Aptr + kt * 32 + q * 4)
                               : make_float4(0.f, 0.f, 0.f, 0.f);
            if (ELU_A) {
                #pragma unroll
                for (int q = 0; q < 4; q++) {
                    f[q].x = elu1(f[q].x); f[q].y = elu1(f[q].y);
                    f[q].z = elu1(f[q].z); f[q].w = elu1(f[q].w);
                }
            }
            unsigned* hp = sAhi + arow * AS_STRIDE + (ak0 >> 1);
            unsigned* lp = sAlo + arow * AS_STRIDE + (ak0 >> 1);
            #pragma unroll
            for (int q = 0; q < 4; q++) {
                unsigned h0, l0, h1, l1;
                bf16_split(f[q].x, f[q].y, h0, l0);
                bf16_split(f[q].z, f[q].w, h1, l1);
                hp[q * 2] = h0; hp[q * 2 + 1] = h1;
                lp[q * 2] = l0; lp[q * 2 + 1] = l1;
            }
        }
        {
            const unsigned* gh = Bhi + (size_t)(kt * 16 + bkp) * Nc + colB + bn0;
            const unsigned* gl = Blo + (size_t)(kt * 16 + bkp) * Nc + colB + bn0;
            unsigned* sh = sBhi + bkp * BS_STRIDE + bn0;
            unsigned* sl = sBlo + bkp * BS_STRIDE + bn0;
            #pragma unroll
            for (int q = 0; q < BN / 64; q++) {
                ((int4*)sh)[q] = ((const int4*)gh)[q];
                ((int4*)sl)[q] = ((const int4*)gl)[q];
            }
        }
        __syncthreads();

        #pragma unroll
        for (int s = 0; s < 2; s++) {
            const int kp = s * 8 + tig;
            unsigned ahi[2][4], alo[2][4];
            #pragma unroll
            for (int am = 0; am < 2; am++) {
                int m0 = wm + am * 16 + g;
                ahi[am][0] = sAhi[m0 * AS_STRIDE + kp];
                ahi[am][1] = sAhi[(m0 + 8) * AS_STRIDE + kp];
                ahi[am][2] = sAhi[m0 * AS_STRIDE + kp + 4];
                ahi[am][3] = sAhi[(m0 + 8) * AS_STRIDE + kp + 4];
                alo[am][0] = sAlo[m0 * AS_STRIDE + kp];
                alo[am][1] = sAlo[(m0 + 8) * AS_STRIDE + kp];
                alo[am][2] = sAlo[m0 * AS_STRIDE + kp + 4];
                alo[am][3] = sAlo[(m0 + 8) * AS_STRIDE + kp + 4];
            }
            #pragma unroll
            for (int an = 0; an < NATOM; an++) {
                int n = wn + an * 8 + g;
                unsigned bh0 = sBhi[kp * BS_STRIDE + n];
                unsigned bh1 = sBhi[(kp + 4) * BS_STRIDE + n];
                unsigned bl0 = sBlo[kp * BS_STRIDE + n];
                unsigned bl1 = sBlo[(kp + 4) * BS_STRIDE + n];
                #pragma unroll
                for (int am = 0; am < 2; am++) {
                    MMA_BF16(d[am][an], ahi[am], bh0, bh1);
                    MMA_BF16(d[am][an], alo[am], bh0, bh1);
                    MMA_BF16(d[am][an], ahi[am], bl0, bl1);
                }
            }
        }
        __syncthreads();
    }

    #pragma unroll
    for (int am = 0; am < 2; am++) {
        int r0 = rowA + wm + am * 16 + g;
        #pragma unroll
        for (int an = 0; an < NATOM; an++) {
            int c = colB + wn + an * 8 + 2 * tig;
            if (r0 < M)
                *(float2*)&C[(size_t)r0 * Nc + c] = make_float2(d[am][an][0], d[am][an][1]);
            if (r0 + 8 < M)
                *(float2*)&C[(size_t)(r0 + 8) * Nc + c] = make_float2(d[am][an][2], d[am][an][3]);
        }
    }
}

// ---------------- attention dot products -------------------------------------
__global__ void att1_kernel(const float* __restrict__ att_src, const float* __restrict__ att_dst) {
    int idx = blockIdx.x * blockDim.x + threadIdx.x;
    if (idx >= N_NODES * HEADS) return;
    int n = idx >> 3, h = idx & 7;
    const float4* hp = (const float4*)(g_h1 + (size_t)n * F1 + h * HID);
    const float4* as = (const float4*)(att_src + h * HID);
    const float4* ad = (const float4*)(att_dst + h * HID);
    float s = 0.f, d = 0.f;
    #pragma unroll
    for (int i = 0; i < 8; i++) {
        float4 hv = hp[i], a = as[i], b = ad[i];
        s += hv.x * a.x + hv.y * a.y + hv.z * a.z + hv.w * a.w;
        d += hv.x * b.x + hv.y * b.y + hv.z * b.z + hv.w * b.w;
    }
    g_asrc1[idx] = s;
    g_adst1[idx] = d;
}

__global__ void att2_kernel(const float* __restrict__ att_src, const float* __restrict__ att_dst) {
    int n = blockIdx.x * blockDim.x + threadIdx.x;
    if (n >= N_NODES) return;
    const float4* hp = (const float4*)(g_h2 + (size_t)n * OUT_C);
    const float4* as = (const float4*)att_src;
    const float4* ad = (const float4*)att_dst;
    float s = 0.f, d = 0.f;
    #pragma unroll
    for (int i = 0; i < 16; i++) {
        float4 hv = hp[i], a = as[i], b = ad[i];
        s += hv.x * a.x + hv.y * a.y + hv.z * a.z + hv.w * a.w;
        d += hv.x * b.x + hv.y * b.y + hv.z * b.z + hv.w * b.w;
    }
    g_asrc2[n] = s;
    g_adst2[n] = d;
}

// ---------------- GAT layer 1: warp per (node, half-features) ----------------
// Each warp handles 128 floats (4 heads). lane covers float4 at
// [half*128 + lane*4], head = half*4 + (lane>>3).
__global__ __launch_bounds__(256) void gat1_csr(const float* __restrict__ b1) {
    int gw = blockIdx.x * 8 + (threadIdx.x >> 5);   // global warp
    int lane = threadIdx.x & 31;
    int n = gw >> 1, half = gw & 1;
    if (n >= N_NODES) return;
    int beg = g_start[n], end = g_start[n + 1];

    // pass 1: denominators for this half's 4 heads; lane = (eg:3 | h:2)
    int h2 = lane & 3;                 // head within half
    int eg = lane >> 2;                // 8 edge groups
    int ghd = half * 4 + h2;
    float adst_p1 = g_adst1[n * 8 + ghd];
    float den = 0.f;
    for (int e0 = beg; e0 < end; e0 += 8) {
        int e = e0 + eg;
        if (e < end) {
            int s = g_csr_src[e];
            den += __expf(lrelu(g_asrc1[s * 8 + ghd] + adst_p1));
        }
    }
    den += __shfl_xor_sync(0xffffffffu, den, 4);
    den += __shfl_xor_sync(0xffffffffu, den, 8);
    den += __shfl_xor_sync(0xffffffffu, den, 16);
    // pass-2 lane needs head (lane>>3); its den sits in lane (lane>>3)
    int hh = lane >> 3;                                 // 0..3
    float inv = 1.f / (__shfl_sync(0xffffffffu, den, hh) + EPS_F);
    int head = half * 4 + hh;
    float adst_h = g_adst1[n * 8 + head];

    // pass 2: accumulate alpha * h1[src] (one float4 per lane)
    float4 a0 = make_float4(0.f, 0.f, 0.f, 0.f);
    const float* h1base = g_h1 + half * 128 + lane * 4;
    #pragma unroll 4
    for (int e = beg; e < end; e++) {
        int s = g_csr_src[e];
        float alpha = __expf(lrelu(g_asrc1[s * 8 + head] + adst_h)) * inv;
        float4 v = *(const float4*)(h1base + (size_t)s * F1);
        a0.x += alpha * v.x; a0.y += alpha * v.y;
        a0.z += alpha * v.z; a0.w += alpha * v.w;
    }
    float4 bb = *(const float4*)(b1 + half * 128 + lane * 4);
    *(float4*)(g_out1 + (size_t)n * F1 + half * 128 + lane * 4) =
        make_float4(bb.x + a0.x, bb.y + a0.y, bb.z + a0.z, bb.w + a0.w);
}

// ---------------- GAT layer 2: warp per (node, half-features) ----------------
__global__ __launch_bounds__(256) void gat2_csr(float* __restrict__ emb, const float* __restrict__ b2) {
    int gw = blockIdx.x * 8 + (threadIdx.x >> 5);
    int lane = threadIdx.x & 31;
    int n = gw >> 1, half = gw & 1;
    if (n >= N_NODES) return;
    int beg = g_start[n], end = g_start[n + 1];
    float adst = g_adst2[n];

    float den = 0.f;
    for (int e = beg + lane; e < end; e += 32)
        den += __expf(lrelu(g_asrc2[g_csr_src[e]] + adst));
    #pragma unroll
    for (int m = 16; m >= 1; m >>= 1) den += __shfl_xor_sync(0xffffffffu, den, m);
    float inv = 1.f / (den + EPS_F);

    float acc = 0.f;
    const float* h2base = g_h2 + half * 32 + lane;
    #pragma unroll 4
    for (int e = beg; e < end; e++) {
        int s = g_csr_src[e];
        float alpha = __expf(lrelu(g_asrc2[s] + adst)) * inv;
        acc += alpha * h2base[(size_t)s * OUT_C];
    }
    int col = half * 32 + lane;
    emb[(size_t)n * OUT_C + col] = b2[col] + acc;
}

// ---------------- fused MLP head + softmax (64 nodes/block) ------------------
__global__ __launch_bounds__(256) void mlp_kernel(
    const float* __restrict__ emb,
    const float* __restrict__ Wm1, const float* __restrict__ bm1,
    const float* __restrict__ Wm2, const float* __restrict__ bm2,
    float* __restrict__ s_out)
{
    __shared__ float sW1[OUT_C * 128];   // 32 KB
    __shared__ float sW2[128 * K_CL];    // 8 KB
    __shared__ float sb1[128];
    __shared__ float sb2[K_CL];
    __shared__ float sHid[8][128];
    __shared__ float sEmb[8][OUT_C];
    int tid = threadIdx.x;
    for (int i = tid; i < OUT_C * 128; i += 256) sW1[i] = Wm1[i];
    for (int i = tid; i < 128 * K_CL; i += 256) sW2[i] = Wm2[i];
    if (tid < 128) sb1[tid] = bm1[tid];
    if (tid < K_CL) sb2[tid] = bm2[tid];
    __syncthreads();
    int warp = tid >> 5, lane = tid & 31;
    #pragma unroll
    for (int it = 0; it < 8; it++) {
        int n = blockIdx.x * 64 + it * 8 + warp;
        if (n >= N_NODES) continue;
        float2 e2 = *(const float2*)(emb + (size_t)n * OUT_C + lane * 2);
        sEmb[warp][lane * 2] = e2.x;
        sEmb[warp][lane * 2 + 1] = e2.y;
        __syncwarp();
        #pragma unroll
        for (int w = 0; w < 4; w++) {
            int j = lane + w * 32;
            float acc = sb1[j];
            #pragma unroll 8
            for (int c = 0; c < OUT_C; c++) acc += sEmb[warp][c] * sW1[c * 128 + j];
            sHid[warp][j] = fmaxf(acc, 0.f);
        }
        __syncwarp();
        if (lane < K_CL) {
            float lg = sb2[lane];
            #pragma unroll 16
            for (int k = 0; k < 128; k++) lg += sHid[warp][k] * sW2[k * K_CL + lane];
            float mx = lg;
            #pragma unroll
            for (int m = 8; m >= 1; m >>= 1)
                mx = fmaxf(mx, __shfl_xor_sync(0xffff, mx, m, 16));
            float ev = __expf(lg - mx);
            float sum = ev;
            #pragma unroll
            for (int m = 8; m >= 1; m >>= 1)
                sum += __shfl_xor_sync(0xffff, sum, m, 16);
            s_out[(size_t)n * K_CL + lane] = ev / sum;
        }
        __syncwarp();
    }
}

// ---------------- launch ------------------------------------------------------
extern "C" void kernel_launch(void* const* d_in, const int* in_sizes, int n_in,
                              void* d_out, int out_size) {
    const float* x        = (const float*)d_in[0];
    const int*   ei       = (const int*)d_in[1];     // [2, E]: src then dst
    const float* W1       = (const float*)d_in[2];
    const float* att_src1 = (const float*)d_in[3];
    const float* att_dst1 = (const float*)d_in[4];
    const float* b1       = (const float*)d_in[5];
    const float* W2       = (const float*)d_in[6];
    const float* att_src2 = (const float*)d_in[7];
    const float* att_dst2 = (const float*)d_in[8];
    const float* b2       = (const float*)d_in[9];
    const float* Wm1      = (const float*)d_in[10];
    const float* bm1      = (const float*)d_in[11];
    const float* Wm2      = (const float*)d_in[12];
    const float* bm2      = (const float*)d_in[13];

    float* s_out = (float*)d_out;                           // [N, 16]
    float* emb   = (float*)d_out + (size_t)N_NODES * K_CL;  // [N, 64]

    float *ph1, *pout1, *ph2;
    cudaGetSymbolAddress((void**)&ph1, g_h1);
    cudaGetSymbolAddress((void**)&pout1, g_out1);
    cudaGetSymbolAddress((void**)&ph2, g_h2);
    unsigned *pw1hi, *pw1lo, *pw2hi, *pw2lo;
    cudaGetSymbolAddress((void**)&pw1hi, g_w1hi);
    cudaGetSymbolAddress((void**)&pw1lo, g_w1lo);
    cudaGetSymbolAddress((void**)&pw2hi, g_w2hi);
    cudaGetSymbolAddress((void**)&pw2lo, g_w2lo);

    const int NSCAN = (N_NODES + 255) / 256;   // 196

    // 1. prep: zero deg histogram + split W1/W2 to bf16 hi/lo (one kernel)
    prep_kernel<<<292, 256>>>(W1, W2);
    // 2. CSR build
    hist_kernel<<<(ETOT + 255) / 256, 256>>>(ei);
    scan1_kernel<<<NSCAN, 256>>>();
    scan2_kernel<<<1, 256>>>(NSCAN);
    scan3_kernel<<<NSCAN, 256>>>();
    scatter_kernel<<<(ETOT + 255) / 256, 256>>>(ei);

    // 3. h1 = x @ W1   [50000,128]x[128,256]  (bf16 3-product tensor cores)
    {
        dim3 grid(F1 / 128, (N_NODES + 127) / 128);
        gemm_bf16x3<128, false><<<grid, 256>>>(x, pw1hi, pw1lo, ph1, N_NODES, F1, IN_C);
    }
    // 4. attention dots layer 1
    att1_kernel<<<(N_NODES * HEADS + 255) / 256, 256>>>(att_src1, att_dst1);
    // 5. GAT layer 1 (warp per node-half; b1 folded)
    gat1_csr<<<(N_NODES * 2 + 7) / 8, 256>>>(b1);
    // 6. h2 = ELU(out1) @ W2  [50000,256]x[256,64]  (ELU fused into A-split)
    {
        dim3 grid(OUT_C / 64, (N_NODES + 127) / 128);
        gemm_bf16x3<64, true><<<grid, 256>>>(pout1, pw2hi, pw2lo, ph2, N_NODES, OUT_C, F1);
    }
    // 7. attention dots layer 2
    att2_kernel<<<(N_NODES + 255) / 256, 256>>>(att_src2, att_dst2);
    // 8. GAT layer 2 (warp per node-half) -> embeddings (b2 folded)
    gat2_csr<<<(N_NODES * 2 + 7) / 8, 256>>>(emb, b2);
    // 9. MLP head + softmax -> s
    mlp_kernel<<<(N_NODES + 63) / 64, 256>>>(emb, Wm1, bm1, Wm2, bm2, s_out);
}

// round 14
// speedup vs baseline: 1.0868x; 1.0868x over previous
#include <cuda_runtime.h>
#include <math.h>

#define N_NODES 50000
#define NUM_E   400000
#define ETOT    (NUM_E + N_NODES)   // 450000, self-loops appended
#define IN_C    128
#define HID     32
#define HEADS   8
#define F1      (HEADS * HID)       // 256
#define OUT_C   64
#define K_CL    16
#define NEG_SLOPE 0.2f
#define EPS_F   1e-16f

// ---------------- scratch (device globals; no runtime allocation) -----------
__device__ float g_h1[(size_t)N_NODES * F1];     // x@W1
__device__ float g_out1[(size_t)N_NODES * F1];   // layer1 output (incl. b1)
__device__ float g_h2[(size_t)N_NODES * OUT_C];  // ELU(out1)@W2
__device__ float g_asrc1[N_NODES * HEADS];
__device__ float g_adst1[N_NODES * HEADS];
__device__ float g_asrc2[N_NODES];
__device__ float g_adst2[N_NODES];
// CSR by destination
__device__ int g_deg[N_NODES];
__device__ int g_start[N_NODES + 1];
__device__ int g_cursor[N_NODES];
__device__ int g_csr_src[ETOT];
__device__ int g_bsum[256];
// pre-split weights (packed bf16x2 along k-pairs): [K/2][N]
__device__ unsigned g_w1hi[(IN_C / 2) * F1];
__device__ unsigned g_w1lo[(IN_C / 2) * F1];
__device__ unsigned g_w2hi[(F1 / 2) * OUT_C];
__device__ unsigned g_w2lo[(F1 / 2) * OUT_C];

// ---------------- helpers ----------------------------------------------------
__device__ __forceinline__ float lrelu(float x) { return x > 0.f ? x : NEG_SLOPE * x; }
__device__ __forceinline__ float elu1(float x)  { return x > 0.f ? x : expm1f(x); }

__device__ __forceinline__ unsigned pack_bf16(float f_even, float f_odd) {
    unsigned r;
    asm("cvt.rn.satfinite.bf16x2.f32 %0, %1, %2;" : "=r"(r) : "f"(f_odd), "f"(f_even));
    return r;
}
__device__ __forceinline__ void bf16_split(float f0, float f1, unsigned& hi, unsigned& lo) {
    hi = pack_bf16(f0, f1);
    float b0 = __uint_as_float(hi << 16);
    float b1 = __uint_as_float(hi & 0xffff0000u);
    lo = pack_bf16(f0 - b0, f1 - b1);
}

#define MMA_BF16(d, a, b0_, b1_) \
    asm("mma.sync.aligned.m16n8k16.row.col.f32.bf16.bf16.f32 " \
        "{%0,%1,%2,%3}, {%4,%5,%6,%7}, {%8,%9}, {%0,%1,%2,%3};" \
        : "+f"(d[0]), "+f"(d[1]), "+f"(d[2]), "+f"(d[3]) \
        : "r"(a[0]), "r"(a[1]), "r"(a[2]), "r"(a[3]), "r"(b0_), "r"(b1_))

// ---------------- prep: zero degree hist + split both weight matrices --------
__global__ void prep_kernel(const float* __restrict__ W1, const float* __restrict__ W2) {
    int b = blockIdx.x, tid = threadIdx.x;
    if (b < 196) {
        int i = b * 256 + tid;
        if (i < N_NODES) g_deg[i] = 0;
    } else if (b < 196 + 64) {               // W1: (IN_C/2)*F1 = 16384 = 64*256
        int i = (b - 196) * 256 + tid;
        int kp = i >> 8, n = i & 255;
        unsigned h, l;
        bf16_split(W1[(size_t)(2 * kp) * F1 + n], W1[(size_t)(2 * kp + 1) * F1 + n], h, l);
        g_w1hi[i] = h; g_w1lo[i] = l;
    } else {                                  // W2: (F1/2)*OUT_C = 8192 = 32*256
        int i = (b - 260) * 256 + tid;
        int kp = i >> 6, n = i & 63;
        unsigned h, l;
        bf16_split(W2[(size_t)(2 * kp) * OUT_C + n], W2[(size_t)(2 * kp + 1) * OUT_C + n], h, l);
        g_w2hi[i] = h; g_w2lo[i] = l;
    }
}

// ---------------- edge histogram ---------------------------------------------
__global__ void hist_kernel(const int* __restrict__ ei) {
    int e = blockIdx.x * blockDim.x + threadIdx.x;
    if (e >= ETOT) return;
    int d = (e < NUM_E) ? ei[NUM_E + e] : e - NUM_E;
    atomicAdd(&g_deg[d], 1);
}

// ---------------- CSR: 3-kernel scan + scatter --------------------------------
__global__ void scan1_kernel() {
    __shared__ int sm[256];
    int tid = threadIdx.x;
    int i = blockIdx.x * 256 + tid;
    int v = (i < N_NODES) ? g_deg[i] : 0;
    sm[tid] = v;
    __syncthreads();
    #pragma unroll
    for (int off = 1; off < 256; off <<= 1) {
        int t = (tid >= off) ? sm[tid - off] : 0;
        __syncthreads();
        sm[tid] += t;
        __syncthreads();
    }
    if (i < N_NODES) g_start[i] = sm[tid] - v;   // exclusive
    if (tid == 255) g_bsum[blockIdx.x] = sm[255];
}
__global__ void scan2_kernel(int nblocks) {
    __shared__ int sm[256];
    int tid = threadIdx.x;
    int v = (tid < nblocks) ? g_bsum[tid] : 0;
    sm[tid] = v;
    __syncthreads();
    #pragma unroll
    for (int off = 1; off < 256; off <<= 1) {
        int t = (tid >= off) ? sm[tid - off] : 0;
        __syncthreads();
        sm[tid] += t;
        __syncthreads();
    }
    if (tid < nblocks) g_bsum[tid] = sm[tid] - v;  // exclusive
}
__global__ void scan3_kernel() {
    int tid = threadIdx.x;
    int i = blockIdx.x * 256 + tid;
    if (i < N_NODES) {
        int s = g_start[i] + g_bsum[blockIdx.x];
        g_start[i] = s;
        g_cursor[i] = s;
    }
    if (i == 0) g_start[N_NODES] = ETOT;
}
__global__ void scatter_kernel(const int* __restrict__ ei) {
    int e = blockIdx.x * blockDim.x + threadIdx.x;
    if (e >= ETOT) return;
    int s, d;
    if (e < NUM_E) { s = ei[e]; d = ei[NUM_E + e]; } else { s = d = e - NUM_E; }
    int pos = atomicAdd(&g_cursor[d], 1);
    g_csr_src[pos] = s;
}

// ---------------- bf16 3-product tensor-core GEMM (reg-prefetch mainloop) ----
#define AS_STRIDE 20
template<int BN, bool ELU_A>
__global__ __launch_bounds__(256, 2) void gemm_bf16x3(
    const float* __restrict__ A,
    const unsigned* __restrict__ Bhi, const unsigned* __restrict__ Blo,
    float* __restrict__ C, int M, int Nc, int Kc)
{
    constexpr int NATOM = BN / 16;
    constexpr int BS_STRIDE = BN + 8;
    constexpr int NBQ = BN / 64;          // int4 chunks per thread for B
    __shared__ unsigned sAhi[128 * AS_STRIDE];
    __shared__ unsigned sAlo[128 * AS_STRIDE];
    __shared__ unsigned sBhi[16 * BS_STRIDE];
    __shared__ unsigned sBlo[16 * BS_STRIDE];

    const int tid = threadIdx.x;
    const int warp = tid >> 5, lane = tid & 31;
    const int g = lane >> 2, tig = lane & 3;
    const int rowA = blockIdx.y * 128, colB = blockIdx.x * BN;
    const int wm = (warp >> 1) * 32, wn = (warp & 1) * (BN / 2);

    float d[2][NATOM][4];
    #pragma unroll
    for (int i = 0; i < 2; i++)
        #pragma unroll
        for (int j = 0; j < NATOM; j++)
            #pragma unroll
            for (int q = 0; q < 4; q++) d[i][j][q] = 0.f;

    const int arow = tid >> 1;
    const int ak0  = (tid & 1) * 16;
    const bool arow_ok = (rowA + arow) < M;
    const float* Aptr = A + (size_t)(rowA + arow) * Kc + ak0;

    const int bkp = tid >> 4;
    const int bn0 = (tid & 15) * (BN / 16);
    unsigned* sh = sBhi + bkp * BS_STRIDE + bn0;
    unsigned* sl = sBlo + bkp * BS_STRIDE + bn0;

    const int KT = Kc / 32;

    // prologue: load tile 0 into registers
    float4 fc[4];
    int4 bhc[NBQ], blc[NBQ];
    #pragma unroll
    for (int q = 0; q < 4; q++)
        fc[q] = arow_ok ? *(const float4*)(Aptr + q * 4) : make_float4(0.f, 0.f, 0.f, 0.f);
    #pragma unroll
    for (int q = 0; q < NBQ; q++) {
        bhc[q] = ((const int4*)(Bhi + (size_t)bkp * Nc + colB + bn0))[q];
        blc[q] = ((const int4*)(Blo + (size_t)bkp * Nc + colB + bn0))[q];
    }

    for (int kt = 0; kt < KT; kt++) {
        // store current tile to smem
        {
            float4 f[4];
            #pragma unroll
            for (int q = 0; q < 4; q++) f[q] = fc[q];
            if (ELU_A) {
                #pragma unroll
                for (int q = 0; q < 4; q++) {
                    f[q].x = elu1(f[q].x); f[q].y = elu1(f[q].y);
                    f[q].z = elu1(f[q].z); f[q].w = elu1(f[q].w);
                }
            }
            unsigned* hp = sAhi + arow * AS_STRIDE + (ak0 >> 1);
            unsigned* lp = sAlo + arow * AS_STRIDE + (ak0 >> 1);
            #pragma unroll
            for (int q = 0; q < 4; q++) {
                unsigned h0, l0, h1, l1;
                bf16_split(f[q].x, f[q].y, h0, l0);
                bf16_split(f[q].z, f[q].w, h1, l1);
                hp[q * 2] = h0; hp[q * 2 + 1] = h1;
                lp[q * 2] = l0; lp[q * 2 + 1] = l1;
            }
            #pragma unroll
            for (int q = 0; q < NBQ; q++) {
                ((int4*)sh)[q] = bhc[q];
                ((int4*)sl)[q] = blc[q];
            }
        }
        __syncthreads();

        // prefetch next tile into registers (overlaps with MMA below)
        if (kt + 1 < KT) {
            #pragma unroll
            for (int q = 0; q < 4; q++)
                fc[q] = arow_ok ? *(const float4*)(Aptr + (kt + 1) * 32 + q * 4)
                                : make_float4(0.f, 0.f, 0.f, 0.f);
            #pragma unroll
            for (int q = 0; q < NBQ; q++) {
                bhc[q] = ((const int4*)(Bhi + (size_t)((kt + 1) * 16 + bkp) * Nc + colB + bn0))[q];
                blc[q] = ((const int4*)(Blo + (size_t)((kt + 1) * 16 + bkp) * Nc + colB + bn0))[q];
            }
        }

        #pragma unroll
        for (int s = 0; s < 2; s++) {
            const int kp = s * 8 + tig;
            unsigned ahi[2][4], alo[2][4];
            #pragma unroll
            for (int am = 0; am < 2; am++) {
                int m0 = wm + am * 16 + g;
                ahi[am][0] = sAhi[m0 * AS_STRIDE + kp];
                ahi[am][1] = sAhi[(m0 + 8) * AS_STRIDE + kp];
                ahi[am][2] = sAhi[m0 * AS_STRIDE + kp + 4];
                ahi[am][3] = sAhi[(m0 + 8) * AS_STRIDE + kp + 4];
                alo[am][0] = sAlo[m0 * AS_STRIDE + kp];
                alo[am][1] = sAlo[(m0 + 8) * AS_STRIDE + kp];
                alo[am][2] = sAlo[m0 * AS_STRIDE + kp + 4];
                alo[am][3] = sAlo[(m0 + 8) * AS_STRIDE + kp + 4];
            }
            #pragma unroll
            for (int an = 0; an < NATOM; an++) {
                int n = wn + an * 8 + g;
                unsigned bh0 = sBhi[kp * BS_STRIDE + n];
                unsigned bh1 = sBhi[(kp + 4) * BS_STRIDE + n];
                unsigned bl0 = sBlo[kp * BS_STRIDE + n];
                unsigned bl1 = sBlo[(kp + 4) * BS_STRIDE + n];
                #pragma unroll
                for (int am = 0; am < 2; am++) {
                    MMA_BF16(d[am][an], ahi[am], bh0, bh1);
                    MMA_BF16(d[am][an], alo[am], bh0, bh1);
                    MMA_BF16(d[am][an], ahi[am], bl0, bl1);
                }
            }
        }
        __syncthreads();
    }

    #pragma unroll
    for (int am = 0; am < 2; am++) {
        int r0 = rowA + wm + am * 16 + g;
        #pragma unroll
        for (int an = 0; an < NATOM; an++) {
            int c = colB + wn + an * 8 + 2 * tig;
            if (r0 < M)
                *(float2*)&C[(size_t)r0 * Nc + c] = make_float2(d[am][an][0], d[am][an][1]);
            if (r0 + 8 < M)
                *(float2*)&C[(size_t)(r0 + 8) * Nc + c] = make_float2(d[am][an][2], d[am][an][3]);
        }
    }
}

// ---------------- attention dot products -------------------------------------
__global__ void att1_kernel(const float* __restrict__ att_src, const float* __restrict__ att_dst) {
    int idx = blockIdx.x * blockDim.x + threadIdx.x;
    if (idx >= N_NODES * HEADS) return;
    int n = idx >> 3, h = idx & 7;
    const float4* hp = (const float4*)(g_h1 + (size_t)n * F1 + h * HID);
    const float4* as = (const float4*)(att_src + h * HID);
    const float4* ad = (const float4*)(att_dst + h * HID);
    float s = 0.f, d = 0.f;
    #pragma unroll
    for (int i = 0; i < 8; i++) {
        float4 hv = hp[i], a = as[i], b = ad[i];
        s += hv.x * a.x + hv.y * a.y + hv.z * a.z + hv.w * a.w;
        d += hv.x * b.x + hv.y * b.y + hv.z * b.z + hv.w * b.w;
    }
    g_asrc1[idx] = s;
    g_adst1[idx] = d;
}

__global__ void att2_kernel(const float* __restrict__ att_src, const float* __restrict__ att_dst) {
    int n = blockIdx.x * blockDim.x + threadIdx.x;
    if (n >= N_NODES) return;
    const float4* hp = (const float4*)(g_h2 + (size_t)n * OUT_C);
    const float4* as = (const float4*)att_src;
    const float4* ad = (const float4*)att_dst;
    float s = 0.f, d = 0.f;
    #pragma unroll
    for (int i = 0; i < 16; i++) {
        float4 hv = hp[i], a = as[i], b = ad[i];
        s += hv.x * a.x + hv.y * a.y + hv.z * a.z + hv.w * a.w;
        d += hv.x * b.x + hv.y * b.y + hv.z * b.z + hv.w * b.w;
    }
    g_asrc2[n] = s;
    g_adst2[n] = d;
}

// ---------------- GAT layer 1: two-pass fused softmax + aggregation ----------
__global__ __launch_bounds__(256) void gat1_csr(const float* __restrict__ b1) {
    int warp = threadIdx.x >> 5, lane = threadIdx.x & 31;
    int n = blockIdx.x * 8 + warp;
    if (n >= N_NODES) return;
    int beg = g_start[n], end = g_start[n + 1];

    // pass 1: denominators for 8 heads; lane = (edge_group:2 | head:3)
    int h8 = lane & 7;
    int eg = lane >> 3;
    float adst_p1 = g_adst1[n * 8 + h8];
    float den = 0.f;
    for (int e0 = beg; e0 < end; e0 += 4) {
        int e = e0 + eg;
        if (e < end) {
            int s = g_csr_src[e];
            den += __expf(lrelu(g_asrc1[s * 8 + h8] + adst_p1));
        }
    }
    den += __shfl_xor_sync(0xffffffffu, den, 8);
    den += __shfl_xor_sync(0xffffffffu, den, 16);
    int head = lane >> 2;
    float inv = 1.f / (__shfl_sync(0xffffffffu, den, head) + EPS_F);
    float adst_h = g_adst1[n * 8 + head];

    // pass 2: accumulate alpha * h1[src] in registers (8 floats/lane)
    float4 a0 = ((const float4*)b1)[lane * 2];
    float4 a1 = ((const float4*)b1)[lane * 2 + 1];
    #pragma unroll 4
    for (int e = beg; e < end; e++) {
        int s = g_csr_src[e];
        float alpha = __expf(lrelu(g_asrc1[s * 8 + head] + adst_h)) * inv;
        const float4* hp = (const float4*)(g_h1 + (size_t)s * F1) + lane * 2;
        float4 v0 = hp[0], v1 = hp[1];
        a0.x += alpha * v0.x; a0.y += alpha * v0.y; a0.z += alpha * v0.z; a0.w += alpha * v0.w;
        a1.x += alpha * v1.x; a1.y += alpha * v1.y; a1.z += alpha * v1.z; a1.w += alpha * v1.w;
    }
    float4* op = (float4*)(g_out1 + (size_t)n * F1) + lane * 2;
    op[0] = a0; op[1] = a1;
}

// ---------------- GAT layer 2: two-pass, writes embeddings -------------------
__global__ __launch_bounds__(256) void gat2_csr(float* __restrict__ emb, const float* __restrict__ b2) {
    int warp = threadIdx.x >> 5, lane = threadIdx.x & 31;
    int n = blockIdx.x * 8 + warp;
    if (n >= N_NODES) return;
    int beg = g_start[n], end = g_start[n + 1];
    float adst = g_adst2[n];

    float den = 0.f;
    for (int e = beg + lane; e < end; e += 32)
        den += __expf(lrelu(g_asrc2[g_csr_src[e]] + adst));
    #pragma unroll
    for (int m = 16; m >= 1; m >>= 1) den += __shfl_xor_sync(0xffffffffu, den, m);
    float inv = 1.f / (den + EPS_F);

    float2 acc = *(const float2*)(b2 + lane * 2);
    #pragma unroll 4
    for (int e = beg; e < end; e++) {
        int s = g_csr_src[e];
        float alpha = __expf(lrelu(g_asrc2[s] + adst)) * inv;
        float2 v = *(const float2*)(g_h2 + (size_t)s * OUT_C + lane * 2);
        acc.x += alpha * v.x;
        acc.y += alpha * v.y;
    }
    *(float2*)(emb + (size_t)n * OUT_C + lane * 2) = acc;
}

// ---------------- fused MLP head + softmax (64 nodes/block) ------------------
__global__ __launch_bounds__(256) void mlp_kernel(
    const float* __restrict__ emb,
    const float* __restrict__ Wm1, const float* __restrict__ bm1,
    const float* __restrict__ Wm2, const float* __restrict__ bm2,
    float* __restrict__ s_out)
{
    __shared__ float sW1[OUT_C * 128];   // 32 KB
    __shared__ float sW2[128 * K_CL];    // 8 KB
    __shared__ float sb1[128];
    __shared__ float sb2[K_CL];
    __shared__ float sHid[8][128];
    __shared__ float sEmb[8][OUT_C];
    int tid = threadIdx.x;
    for (int i = tid; i < OUT_C * 128; i += 256) sW1[i] = Wm1[i];
    for (int i = tid; i < 128 * K_CL; i += 256) sW2[i] = Wm2[i];
    if (tid < 128) sb1[tid] = bm1[tid];
    if (tid < K_CL) sb2[tid] = bm2[tid];
    __syncthreads();
    int warp = tid >> 5, lane = tid & 31;
    #pragma unroll
    for (int it = 0; it < 8; it++) {
        int n = blockIdx.x * 64 + it * 8 + warp;
        if (n >= N_NODES) continue;
        float2 e2 = *(const float2*)(emb + (size_t)n * OUT_C + lane * 2);
        sEmb[warp][lane * 2] = e2.x;
        sEmb[warp][lane * 2 + 1] = e2.y;
        __syncwarp();
        #pragma unroll
        for (int w = 0; w < 4; w++) {
            int j = lane + w * 32;
            float acc = sb1[j];
            #pragma unroll 8
            for (int c = 0; c < OUT_C; c++) acc += sEmb[warp][c] * sW1[c * 128 + j];
            sHid[warp][j] = fmaxf(acc, 0.f);
        }
        __syncwarp();
        if (lane < K_CL) {
            float lg = sb2[lane];
            #pragma unroll 16
            for (int k = 0; k < 128; k++) lg += sHid[warp][k] * sW2[k * K_CL + lane];
            float mx = lg;
            #pragma unroll
            for (int m = 8; m >= 1; m >>= 1)
                mx = fmaxf(mx, __shfl_xor_sync(0xffff, mx, m, 16));
            float ev = __expf(lg - mx);
            float sum = ev;
            #pragma unroll
            for (int m = 8; m >= 1; m >>= 1)
                sum += __shfl_xor_sync(0xffff, sum, m, 16);
            s_out[(size_t)n * K_CL + lane] = ev / sum;
        }
        __syncwarp();
    }
}

// ---------------- side-stream handles (created once; same work every call) ---
static cudaStream_t side_stream() {
    static cudaStream_t s = [] {
        cudaStream_t t;
        cudaStreamCreateWithFlags(&t, cudaStreamNonBlocking);
        return t;
    }();
    return s;
}
static cudaEvent_t fork_event() {
    static cudaEvent_t e = [] {
        cudaEvent_t t;
        cudaEventCreateWithFlags(&t, cudaEventDisableTiming);
        return t;
    }();
    return e;
}
static cudaEvent_t join_event() {
    static cudaEvent_t e = [] {
        cudaEvent_t t;
        cudaEventCreateWithFlags(&t, cudaEventDisableTiming);
        return t;
    }();
    return e;
}

// ---------------- launch ------------------------------------------------------
extern "C" void kernel_launch(void* const* d_in, const int* in_sizes, int n_in,
                              void* d_out, int out_size) {
    const float* x        = (const float*)d_in[0];
    const int*   ei       = (const int*)d_in[1];     // [2, E]: src then dst
    const float* W1       = (const float*)d_in[2];
    const float* att_src1 = (const float*)d_in[3];
    const float* att_dst1 = (const float*)d_in[4];
    const float* b1       = (const float*)d_in[5];
    const float* W2       = (const float*)d_in[6];
    const float* att_src2 = (const float*)d_in[7];
    const float* att_dst2 = (const float*)d_in[8];
    const float* b2       = (const float*)d_in[9];
    const float* Wm1      = (const float*)d_in[10];
    const float* bm1      = (const float*)d_in[11];
    const float* Wm2      = (const float*)d_in[12];
    const float* bm2      = (const float*)d_in[13];

    float* s_out = (float*)d_out;                           // [N, 16]
    float* emb   = (float*)d_out + (size_t)N_NODES * K_CL;  // [N, 64]

    float *ph1, *pout1, *ph2;
    cudaGetSymbolAddress((void**)&ph1, g_h1);
    cudaGetSymbolAddress((void**)&pout1, g_out1);
    cudaGetSymbolAddress((void**)&ph2, g_h2);
    unsigned *pw1hi, *pw1lo, *pw2hi, *pw2lo;
    cudaGetSymbolAddress((void**)&pw1hi, g_w1hi);
    cudaGetSymbolAddress((void**)&pw1lo, g_w1lo);
    cudaGetSymbolAddress((void**)&pw2hi, g_w2hi);
    cudaGetSymbolAddress((void**)&pw2lo, g_w2lo);

    const int NSCAN = (N_NODES + 255) / 256;   // 196
    cudaStream_t s2 = side_stream();
    cudaEvent_t evF = fork_event(), evJ = join_event();

    // 1. prep: zero deg histogram + split W1/W2 to bf16 hi/lo (main stream)
    prep_kernel<<<292, 256>>>(W1, W2);

    // 2. fork: CSR chain on side stream, GEMM1+att1 on main stream (parallel)
    cudaEventRecord(evF, 0);
    cudaStreamWaitEvent(s2, evF, 0);

    hist_kernel<<<(ETOT + 255) / 256, 256, 0, s2>>>(ei);
    scan1_kernel<<<NSCAN, 256, 0, s2>>>();
    scan2_kernel<<<1, 256, 0, s2>>>(NSCAN);
    scan3_kernel<<<NSCAN, 256, 0, s2>>>();

    // main-stream branch: GEMM1 (launch index 5 for ncu -s 5 instrumentation)
    {
        dim3 grid(F1 / 128, (N_NODES + 127) / 128);
        gemm_bf16x3<128, false><<<grid, 256>>>(x, pw1hi, pw1lo, ph1, N_NODES, F1, IN_C);
    }
    scatter_kernel<<<(ETOT + 255) / 256, 256, 0, s2>>>(ei);
    att1_kernel<<<(N_NODES * HEADS + 255) / 256, 256>>>(att_src1, att_dst1);

    // join: gat1 needs both CSR (s2) and att1/h1 (main)
    cudaEventRecord(evJ, s2);
    cudaStreamWaitEvent(0, evJ, 0);

    // 3. GAT layer 1 (b1 folded)
    gat1_csr<<<(N_NODES + 7) / 8, 256>>>(b1);
    // 4. h2 = ELU(out1) @ W2  (ELU fused into A-load)
    {
        dim3 grid(OUT_C / 64, (N_NODES + 127) / 128);
        gemm_bf16x3<64, true><<<grid, 256>>>(pout1, pw2hi, pw2lo, ph2, N_NODES, OUT_C, F1);
    }
    // 5. attention dots layer 2
    att2_kernel<<<(N_NODES + 255) / 256, 256>>>(att_src2, att_dst2);
    // 6. GAT layer 2 -> embeddings (b2 folded)
    gat2_csr<<<(N_NODES + 7) / 8, 256>>>(emb, b2);
    // 7. MLP head + softmax -> s
    mlp_kernel<<<(N_NODES + 63) / 64, 256>>>(emb, Wm1, bm1, Wm2, bm2, s_out);
}

// round 15
// speedup vs baseline: 1.0975x; 1.0098x over previous
#include <cuda_runtime.h>
#include <cuda_fp16.h>
#include <math.h>

#define N_NODES 50000
#define NUM_E   400000
#define ETOT    (NUM_E + N_NODES)   // 450000, self-loops appended
#define IN_C    128
#define HID     32
#define HEADS   8
#define F1      (HEADS * HID)       // 256
#define OUT_C   64
#define K_CL    16
#define NEG_SLOPE 0.2f
#define EPS_F   1e-16f

// ---------------- scratch (device globals; no runtime allocation) -----------
__device__ float g_h1[(size_t)N_NODES * F1];     // x@W1 (fp32)
__device__ __half2 g_h1h[(size_t)N_NODES * (F1 / 2)];    // fp16 mirror for gat1
__device__ float g_out1[(size_t)N_NODES * F1];   // layer1 output (incl. b1)
__device__ float g_h2[(size_t)N_NODES * OUT_C];  // ELU(out1)@W2 (fp32)
__device__ __half2 g_h2h[(size_t)N_NODES * (OUT_C / 2)]; // fp16 mirror for gat2
__device__ float g_asrc1[N_NODES * HEADS];
__device__ float g_adst1[N_NODES * HEADS];
__device__ float g_asrc2[N_NODES];
__device__ float g_adst2[N_NODES];
// CSR by destination
__device__ int g_deg[N_NODES];
__device__ int g_start[N_NODES + 1];
__device__ int g_cursor[N_NODES];
__device__ int g_csr_src[ETOT];
__device__ int g_bsum[256];
// pre-split weights (packed bf16x2 along k-pairs): [K/2][N]
__device__ unsigned g_w1hi[(IN_C / 2) * F1];
__device__ unsigned g_w1lo[(IN_C / 2) * F1];
__device__ unsigned g_w2hi[(F1 / 2) * OUT_C];
__device__ unsigned g_w2lo[(F1 / 2) * OUT_C];

// ---------------- helpers ----------------------------------------------------
__device__ __forceinline__ float lrelu(float x) { return x > 0.f ? x : NEG_SLOPE * x; }
__device__ __forceinline__ float elu1(float x)  { return x > 0.f ? x : expm1f(x); }

__device__ __forceinline__ unsigned pack_bf16(float f_even, float f_odd) {
    unsigned r;
    asm("cvt.rn.satfinite.bf16x2.f32 %0, %1, %2;" : "=r"(r) : "f"(f_odd), "f"(f_even));
    return r;
}
__device__ __forceinline__ void bf16_split(float f0, float f1, unsigned& hi, unsigned& lo) {
    hi = pack_bf16(f0, f1);
    float b0 = __uint_as_float(hi << 16);
    float b1 = __uint_as_float(hi & 0xffff0000u);
    lo = pack_bf16(f0 - b0, f1 - b1);
}

#define MMA_BF16(d, a, b0_, b1_) \
    asm("mma.sync.aligned.m16n8k16.row.col.f32.bf16.bf16.f32 " \
        "{%0,%1,%2,%3}, {%4,%5,%6,%7}, {%8,%9}, {%0,%1,%2,%3};" \
        : "+f"(d[0]), "+f"(d[1]), "+f"(d[2]), "+f"(d[3]) \
        : "r"(a[0]), "r"(a[1]), "r"(a[2]), "r"(a[3]), "r"(b0_), "r"(b1_))

// ---------------- split both weight matrices (main stream) -------------------
__global__ void splitw_kernel(const float* __restrict__ W1, const float* __restrict__ W2) {
    int b = blockIdx.x, tid = threadIdx.x;
    if (b < 64) {                             // W1: (IN_C/2)*F1 = 16384 = 64*256
        int i = b * 256 + tid;
        int kp = i >> 8, n = i & 255;
        unsigned h, l;
        bf16_split(W1[(size_t)(2 * kp) * F1 + n], W1[(size_t)(2 * kp + 1) * F1 + n], h, l);
        g_w1hi[i] = h; g_w1lo[i] = l;
    } else {                                  // W2: (F1/2)*OUT_C = 8192 = 32*256
        int i = (b - 64) * 256 + tid;
        int kp = i >> 6, n = i & 63;
        unsigned h, l;
        bf16_split(W2[(size_t)(2 * kp) * OUT_C + n], W2[(size_t)(2 * kp + 1) * OUT_C + n], h, l);
        g_w2hi[i] = h; g_w2lo[i] = l;
    }
}

// ---------------- zero degree histogram (side stream head) -------------------
__global__ void zero_deg_kernel() {
    int i = blockIdx.x * blockDim.x + threadIdx.x;
    if (i < N_NODES) g_deg[i] = 0;
}

// ---------------- edge histogram ---------------------------------------------
__global__ void hist_kernel(const int* __restrict__ ei) {
    int e = blockIdx.x * blockDim.x + threadIdx.x;
    if (e >= ETOT) return;
    int d = (e < NUM_E) ? ei[NUM_E + e] : e - NUM_E;
    atomicAdd(&g_deg[d], 1);
}

// ---------------- CSR: 3-kernel scan + scatter --------------------------------
__global__ void scan1_kernel() {
    __shared__ int sm[256];
    int tid = threadIdx.x;
    int i = blockIdx.x * 256 + tid;
    int v = (i < N_NODES) ? g_deg[i] : 0;
    sm[tid] = v;
    __syncthreads();
    #pragma unroll
    for (int off = 1; off < 256; off <<= 1) {
        int t = (tid >= off) ? sm[tid - off] : 0;
        __syncthreads();
        sm[tid] += t;
        __syncthreads();
    }
    if (i < N_NODES) g_start[i] = sm[tid] - v;   // exclusive
    if (tid == 255) g_bsum[blockIdx.x] = sm[255];
}
__global__ void scan2_kernel(int nblocks) {
    __shared__ int sm[256];
    int tid = threadIdx.x;
    int v = (tid < nblocks) ? g_bsum[tid] : 0;
    sm[tid] = v;
    __syncthreads();
    #pragma unroll
    for (int off = 1; off < 256; off <<= 1) {
        int t = (tid >= off) ? sm[tid - off] : 0;
        __syncthreads();
        sm[tid] += t;
        __syncthreads();
    }
    if (tid < nblocks) g_bsum[tid] = sm[tid] - v;  // exclusive
}
__global__ void scan3_kernel() {
    int tid = threadIdx.x;
    int i = blockIdx.x * 256 + tid;
    if (i < N_NODES) {
        int s = g_start[i] + g_bsum[blockIdx.x];
        g_start[i] = s;
        g_cursor[i] = s;
    }
    if (i == 0) g_start[N_NODES] = ETOT;
}
__global__ void scatter_kernel(const int* __restrict__ ei) {
    int e = blockIdx.x * blockDim.x + threadIdx.x;
    if (e >= ETOT) return;
    int s, d;
    if (e < NUM_E) { s = ei[e]; d = ei[NUM_E + e]; } else { s = d = e - NUM_E; }
    int pos = atomicAdd(&g_cursor[d], 1);
    g_csr_src[pos] = s;
}

// ---------------- bf16 3-product tensor-core GEMM (reg-prefetch mainloop) ----
#define AS_STRIDE 20
template<int BN, bool ELU_A>
__global__ __launch_bounds__(256, 2) void gemm_bf16x3(
    const float* __restrict__ A,
    const unsigned* __restrict__ Bhi, const unsigned* __restrict__ Blo,
    float* __restrict__ C, int M, int Nc, int Kc)
{
    constexpr int NATOM = BN / 16;
    constexpr int BS_STRIDE = BN + 8;
    constexpr int NBQ = BN / 64;          // int4 chunks per thread for B
    __shared__ unsigned sAhi[128 * AS_STRIDE];
    __shared__ unsigned sAlo[128 * AS_STRIDE];
    __shared__ unsigned sBhi[16 * BS_STRIDE];
    __shared__ unsigned sBlo[16 * BS_STRIDE];

    const int tid = threadIdx.x;
    const int warp = tid >> 5, lane = tid & 31;
    const int g = lane >> 2, tig = lane & 3;
    const int rowA = blockIdx.y * 128, colB = blockIdx.x * BN;
    const int wm = (warp >> 1) * 32, wn = (warp & 1) * (BN / 2);

    float d[2][NATOM][4];
    #pragma unroll
    for (int i = 0; i < 2; i++)
        #pragma unroll
        for (int j = 0; j < NATOM; j++)
            #pragma unroll
            for (int q = 0; q < 4; q++) d[i][j][q] = 0.f;

    const int arow = tid >> 1;
    const int ak0  = (tid & 1) * 16;
    const bool arow_ok = (rowA + arow) < M;
    const float* Aptr = A + (size_t)(rowA + arow) * Kc + ak0;

    const int bkp = tid >> 4;
    const int bn0 = (tid & 15) * (BN / 16);
    unsigned* sh = sBhi + bkp * BS_STRIDE + bn0;
    unsigned* sl = sBlo + bkp * BS_STRIDE + bn0;

    const int KT = Kc / 32;

    // prologue: load tile 0 into registers
    float4 fc[4];
    int4 bhc[NBQ], blc[NBQ];
    #pragma unroll
    for (int q = 0; q < 4; q++)
        fc[q] = arow_ok ? *(const float4*)(Aptr + q * 4) : make_float4(0.f, 0.f, 0.f, 0.f);
    #pragma unroll
    for (int q = 0; q < NBQ; q++) {
        bhc[q] = ((const int4*)(Bhi + (size_t)bkp * Nc + colB + bn0))[q];
        blc[q] = ((const int4*)(Blo + (size_t)bkp * Nc + colB + bn0))[q];
    }

    for (int kt = 0; kt < KT; kt++) {
        {
            float4 f[4];
            #pragma unroll
            for (int q = 0; q < 4; q++) f[q] = fc[q];
            if (ELU_A) {
                #pragma unroll
                for (int q = 0; q < 4; q++) {
                    f[q].x = elu1(f[q].x); f[q].y = elu1(f[q].y);
                    f[q].z = elu1(f[q].z); f[q].w = elu1(f[q].w);
                }
            }
            unsigned* hp = sAhi + arow * AS_STRIDE + (ak0 >> 1);
            unsigned* lp = sAlo + arow * AS_STRIDE + (ak0 >> 1);
            #pragma unroll
            for (int q = 0; q < 4; q++) {
                unsigned h0, l0, h1, l1;
                bf16_split(f[q].x, f[q].y, h0, l0);
                bf16_split(f[q].z, f[q].w, h1, l1);
                hp[q * 2] = h0; hp[q * 2 + 1] = h1;
                lp[q * 2] = l0; lp[q * 2 + 1] = l1;
            }
            #pragma unroll
            for (int q = 0; q < NBQ; q++) {
                ((int4*)sh)[q] = bhc[q];
                ((int4*)sl)[q] = blc[q];
            }
        }
        __syncthreads();

        // prefetch next tile into registers (overlaps with MMA below)
        if (kt + 1 < KT) {
            #pragma unroll
            for (int q = 0; q < 4; q++)
                fc[q] = arow_ok ? *(const float4*)(Aptr + (kt + 1) * 32 + q * 4)
                                : make_float4(0.f, 0.f, 0.f, 0.f);
            #pragma unroll
            for (int q = 0; q < NBQ; q++) {
                bhc[q] = ((const int4*)(Bhi + (size_t)((kt + 1) * 16 + bkp) * Nc + colB + bn0))[q];
                blc[q] = ((const int4*)(Blo + (size_t)((kt + 1) * 16 + bkp) * Nc + colB + bn0))[q];
            }
        }

        #pragma unroll
        for (int s = 0; s < 2; s++) {
            const int kp = s * 8 + tig;
            unsigned ahi[2][4], alo[2][4];
            #pragma unroll
            for (int am = 0; am < 2; am++) {
                int m0 = wm + am * 16 + g;
                ahi[am][0] = sAhi[m0 * AS_STRIDE + kp];
                ahi[am][1] = sAhi[(m0 + 8) * AS_STRIDE + kp];
                ahi[am][2] = sAhi[m0 * AS_STRIDE + kp + 4];
                ahi[am][3] = sAhi[(m0 + 8) * AS_STRIDE + kp + 4];
                alo[am][0] = sAlo[m0 * AS_STRIDE + kp];
                alo[am][1] = sAlo[(m0 + 8) * AS_STRIDE + kp];
                alo[am][2] = sAlo[m0 * AS_STRIDE + kp + 4];
                alo[am][3] = sAlo[(m0 + 8) * AS_STRIDE + kp + 4];
            }
            #pragma unroll
            for (int an = 0; an < NATOM; an++) {
                int n = wn + an * 8 + g;
                unsigned bh0 = sBhi[kp * BS_STRIDE + n];
                unsigned bh1 = sBhi[(kp + 4) * BS_STRIDE + n];
                unsigned bl0 = sBlo[kp * BS_STRIDE + n];
                unsigned bl1 = sBlo[(kp + 4) * BS_STRIDE + n];
                #pragma unroll
                for (int am = 0; am < 2; am++) {
                    MMA_BF16(d[am][an], ahi[am], bh0, bh1);
                    MMA_BF16(d[am][an], alo[am], bh0, bh1);
                    MMA_BF16(d[am][an], ahi[am], bl0, bl1);
                }
            }
        }
        __syncthreads();
    }

    #pragma unroll
    for (int am = 0; am < 2; am++) {
        int r0 = rowA + wm + am * 16 + g;
        #pragma unroll
        for (int an = 0; an < NATOM; an++) {
            int c = colB + wn + an * 8 + 2 * tig;
            if (r0 < M)
                *(float2*)&C[(size_t)r0 * Nc + c] = make_float2(d[am][an][0], d[am][an][1]);
            if (r0 + 8 < M)
                *(float2*)&C[(size_t)(r0 + 8) * Nc + c] = make_float2(d[am][an][2], d[am][an][3]);
        }
    }
}

// ---------------- attention dots layer 1 + fp16 mirror of h1 -----------------
__global__ void att1_kernel(const float* __restrict__ att_src, const float* __restrict__ att_dst) {
    int idx = blockIdx.x * blockDim.x + threadIdx.x;
    if (idx >= N_NODES * HEADS) return;
    int n = idx >> 3, h = idx & 7;
    const float4* hp = (const float4*)(g_h1 + (size_t)n * F1 + h * HID);
    const float4* as = (const float4*)(att_src + h * HID);
    const float4* ad = (const float4*)(att_dst + h * HID);
    float s = 0.f, d = 0.f;
    __half2 mir[16];
    #pragma unroll
    for (int i = 0; i < 8; i++) {
        float4 hv = hp[i], a = as[i], b = ad[i];
        s += hv.x * a.x + hv.y * a.y + hv.z * a.z + hv.w * a.w;
        d += hv.x * b.x + hv.y * b.y + hv.z * b.z + hv.w * b.w;
        mir[2 * i]     = __floats2half2_rn(hv.x, hv.y);
        mir[2 * i + 1] = __floats2half2_rn(hv.z, hv.w);
    }
    g_asrc1[idx] = s;
    g_adst1[idx] = d;
    uint4* dst = (uint4*)(g_h1h + (size_t)n * (F1 / 2) + h * 16);
    const uint4* srcp = (const uint4*)mir;
    #pragma unroll
    for (int q = 0; q < 4; q++) dst[q] = srcp[q];
}

// ---------------- attention dots layer 2 + fp16 mirror of h2 -----------------
__global__ void att2_kernel(const float* __restrict__ att_src, const float* __restrict__ att_dst) {
    int n = blockIdx.x * blockDim.x + threadIdx.x;
    if (n >= N_NODES) return;
    const float4* hp = (const float4*)(g_h2 + (size_t)n * OUT_C);
    const float4* as = (const float4*)att_src;
    const float4* ad = (const float4*)att_dst;
    float s = 0.f, d = 0.f;
    __half2 mir[32];
    #pragma unroll
    for (int i = 0; i < 16; i++) {
        float4 hv = hp[i], a = as[i], b = ad[i];
        s += hv.x * a.x + hv.y * a.y + hv.z * a.z + hv.w * a.w;
        d += hv.x * b.x + hv.y * b.y + hv.z * b.z + hv.w * b.w;
        mir[2 * i]     = __floats2half2_rn(hv.x, hv.y);
        mir[2 * i + 1] = __floats2half2_rn(hv.z, hv.w);
    }
    g_asrc2[n] = s;
    g_adst2[n] = d;
    uint4* dst = (uint4*)(g_h2h + (size_t)n * (OUT_C / 2));
    const uint4* srcp = (const uint4*)mir;
    #pragma unroll
    for (int q = 0; q < 8; q++) dst[q] = srcp[q];
}

// ---------------- GAT layer 1: two-pass, fp16 gathers -------------------------
__global__ __launch_bounds__(256) void gat1_csr(const float* __restrict__ b1) {
    int warp = threadIdx.x >> 5, lane = threadIdx.x & 31;
    int n = blockIdx.x * 8 + warp;
    if (n >= N_NODES) return;
    int beg = g_start[n], end = g_start[n + 1];

    // pass 1: denominators for 8 heads; lane = (edge_group:2 | head:3)
    int h8 = lane & 7;
    int eg = lane >> 3;
    float adst_p1 = g_adst1[n * 8 + h8];
    float den = 0.f;
    for (int e0 = beg; e0 < end; e0 += 4) {
        int e = e0 + eg;
        if (e < end) {
            int s = g_csr_src[e];
            den += __expf(lrelu(g_asrc1[s * 8 + h8] + adst_p1));
        }
    }
    den += __shfl_xor_sync(0xffffffffu, den, 8);
    den += __shfl_xor_sync(0xffffffffu, den, 16);
    int head = lane >> 2;
    float inv = 1.f / (__shfl_sync(0xffffffffu, den, head) + EPS_F);
    float adst_h = g_adst1[n * 8 + head];

    // pass 2: accumulate alpha * h1[src] (fp16 gathers, 16 B/lane/edge)
    float4 a0 = ((const float4*)b1)[lane * 2];
    float4 a1 = ((const float4*)b1)[lane * 2 + 1];
    #pragma unroll 4
    for (int e = beg; e < end; e++) {
        int s = g_csr_src[e];
        float alpha = __expf(lrelu(g_asrc1[s * 8 + head] + adst_h)) * inv;
        uint4 raw = *(const uint4*)(g_h1h + (size_t)s * (F1 / 2) + lane * 4);
        float2 f0 = __half22float2(*reinterpret_cast<__half2*>(&raw.x));
        float2 f1 = __half22float2(*reinterpret_cast<__half2*>(&raw.y));
        float2 f2 = __half22float2(*reinterpret_cast<__half2*>(&raw.z));
        float2 f3 = __half22float2(*reinterpret_cast<__half2*>(&raw.w));
        a0.x += alpha * f0.x; a0.y += alpha * f0.y;
        a0.z += alpha * f1.x; a0.w += alpha * f1.y;
        a1.x += alpha * f2.x; a1.y += alpha * f2.y;
        a1.z += alpha * f3.x; a1.w += alpha * f3.y;
    }
    float4* op = (float4*)(g_out1 + (size_t)n * F1) + lane * 2;
    op[0] = a0; op[1] = a1;
}

// ---------------- GAT layer 2: two-pass, fp16 gathers -------------------------
__global__ __launch_bounds__(256) void gat2_csr(float* __restrict__ emb, const float* __restrict__ b2) {
    int warp = threadIdx.x >> 5, lane = threadIdx.x & 31;
    int n = blockIdx.x * 8 + warp;
    if (n >= N_NODES) return;
    int beg = g_start[n], end = g_start[n + 1];
    float adst = g_adst2[n];

    float den = 0.f;
    for (int e = beg + lane; e < end; e += 32)
        den += __expf(lrelu(g_asrc2[g_csr_src[e]] + adst));
    #pragma unroll
    for (int m = 16; m >= 1; m >>= 1) den += __shfl_xor_sync(0xffffffffu, den, m);
    float inv = 1.f / (den + EPS_F);

    float2 acc = *(const float2*)(b2 + lane * 2);
    #pragma unroll 4
    for (int e = beg; e < end; e++) {
        int s = g_csr_src[e];
        float alpha = __expf(lrelu(g_asrc2[s] + adst)) * inv;
        float2 v = __half22float2(g_h2h[(size_t)s * (OUT_C / 2) + lane]);
        acc.x += alpha * v.x;
        acc.y += alpha * v.y;
    }
    *(float2*)(emb + (size_t)n * OUT_C + lane * 2) = acc;
}

// ---------------- fused MLP head + softmax (64 nodes/block) ------------------
__global__ __launch_bounds__(256) void mlp_kernel(
    const float* __restrict__ emb,
    const float* __restrict__ Wm1, const float* __restrict__ bm1,
    const float* __restrict__ Wm2, const float* __restrict__ bm2,
    float* __restrict__ s_out)
{
    __shared__ float sW1[OUT_C * 128];   // 32 KB
    __shared__ float sW2[128 * K_CL];    // 8 KB
    __shared__ float sb1[128];
    __shared__ float sb2[K_CL];
    __shared__ float sHid[8][128];
    __shared__ float sEmb[8][OUT_C];
    int tid = threadIdx.x;
    for (int i = tid; i < OUT_C * 128; i += 256) sW1[i] = Wm1[i];
    for (int i = tid; i < 128 * K_CL; i += 256) sW2[i] = Wm2[i];
    if (tid < 128) sb1[tid] = bm1[tid];
    if (tid < K_CL) sb2[tid] = bm2[tid];
    __syncthreads();
    int warp = tid >> 5, lane = tid & 31;
    #pragma unroll
    for (int it = 0; it < 8; it++) {
        int n = blockIdx.x * 64 + it * 8 + warp;
        if (n >= N_NODES) continue;
        float2 e2 = *(const float2*)(emb + (size_t)n * OUT_C + lane * 2);
        sEmb[warp][lane * 2] = e2.x;
        sEmb[warp][lane * 2 + 1] = e2.y;
        __syncwarp();
        #pragma unroll
        for (int w = 0; w < 4; w++) {
            int j = lane + w * 32;
            float acc = sb1[j];
            #pragma unroll 8
            for (int c = 0; c < OUT_C; c++) acc += sEmb[warp][c] * sW1[c * 128 + j];
            sHid[warp][j] = fmaxf(acc, 0.f);
        }
        __syncwarp();
        if (lane < K_CL) {
            float lg = sb2[lane];
            #pragma unroll 16
            for (int k = 0; k < 128; k++) lg += sHid[warp][k] * sW2[k * K_CL + lane];
            float mx = lg;
            #pragma unroll
            for (int m = 8; m >= 1; m >>= 1)
                mx = fmaxf(mx, __shfl_xor_sync(0xffff, mx, m, 16));
            float ev = __expf(lg - mx);
            float sum = ev;
            #pragma unroll
            for (int m = 8; m >= 1; m >>= 1)
                sum += __shfl_xor_sync(0xffff, sum, m, 16);
            s_out[(size_t)n * K_CL + lane] = ev / sum;
        }
        __syncwarp();
    }
}

// ---------------- side-stream handles (created once; same work every call) ---
static cudaStream_t side_stream() {
    static cudaStream_t s = [] {
        cudaStream_t t;
        cudaStreamCreateWithFlags(&t, cudaStreamNonBlocking);
        return t;
    }();
    return s;
}
static cudaEvent_t fork_event() {
    static cudaEvent_t e = [] {
        cudaEvent_t t;
        cudaEventCreateWithFlags(&t, cudaEventDisableTiming);
        return t;
    }();
    return e;
}
static cudaEvent_t join_event() {
    static cudaEvent_t e = [] {
        cudaEvent_t t;
        cudaEventCreateWithFlags(&t, cudaEventDisableTiming);
        return t;
    }();
    return e;
}

// ---------------- launch ------------------------------------------------------
extern "C" void kernel_launch(void* const* d_in, const int* in_sizes, int n_in,
                              void* d_out, int out_size) {
    const float* x        = (const float*)d_in[0];
    const int*   ei       = (const int*)d_in[1];     // [2, E]: src then dst
    const float* W1       = (const float*)d_in[2];
    const float* att_src1 = (const float*)d_in[3];
    const float* att_dst1 = (const float*)d_in[4];
    const float* b1       = (const float*)d_in[5];
    const float* W2       = (const float*)d_in[6];
    const float* att_src2 = (const float*)d_in[7];
    const float* att_dst2 = (const float*)d_in[8];
    const float* b2       = (const float*)d_in[9];
    const float* Wm1      = (const float*)d_in[10];
    const float* bm1      = (const float*)d_in[11];
    const float* Wm2      = (const float*)d_in[12];
    const float* bm2      = (const float*)d_in[13];

    float* s_out = (float*)d_out;                           // [N, 16]
    float* emb   = (float*)d_out + (size_t)N_NODES * K_CL;  // [N, 64]

    float *ph1, *pout1, *ph2;
    cudaGetSymbolAddress((void**)&ph1, g_h1);
    cudaGetSymbolAddress((void**)&pout1, g_out1);
    cudaGetSymbolAddress((void**)&ph2, g_h2);
    unsigned *pw1hi, *pw1lo, *pw2hi, *pw2lo;
    cudaGetSymbolAddress((void**)&pw1hi, g_w1hi);
    cudaGetSymbolAddress((void**)&pw1lo, g_w1lo);
    cudaGetSymbolAddress((void**)&pw2hi, g_w2hi);
    cudaGetSymbolAddress((void**)&pw2lo, g_w2lo);

    const int NSCAN = (N_NODES + 255) / 256;   // 196
    cudaStream_t s2 = side_stream();
    cudaEvent_t evF = fork_event(), evJ = join_event();

    // fork immediately: CSR chain on side stream, GEMM path on main stream
    cudaEventRecord(evF, 0);
    cudaStreamWaitEvent(s2, evF, 0);

    // side stream: zero deg -> hist -> scan -> scatter
    zero_deg_kernel<<<NSCAN, 256, 0, s2>>>();
    hist_kernel<<<(ETOT + 255) / 256, 256, 0, s2>>>(ei);
    scan1_kernel<<<NSCAN, 256, 0, s2>>>();
    scan2_kernel<<<1, 256, 0, s2>>>(NSCAN);
    scan3_kernel<<<NSCAN, 256, 0, s2>>>();
    scatter_kernel<<<(ETOT + 255) / 256, 256, 0, s2>>>(ei);

    // main stream: weight splits -> GEMM1 -> att1 (+ fp16 mirror)
    splitw_kernel<<<96, 256>>>(W1, W2);
    {
        dim3 grid(F1 / 128, (N_NODES + 127) / 128);
        gemm_bf16x3<128, false><<<grid, 256>>>(x, pw1hi, pw1lo, ph1, N_NODES, F1, IN_C);
    }
    att1_kernel<<<(N_NODES * HEADS + 255) / 256, 256>>>(att_src1, att_dst1);

    // join: gat1 needs both CSR (s2) and att1/h1h (main)
    cudaEventRecord(evJ, s2);
    cudaStreamWaitEvent(0, evJ, 0);

    // GAT layer 1 (b1 folded, fp16 gathers)
    gat1_csr<<<(N_NODES + 7) / 8, 256>>>(b1);
    // h2 = ELU(out1) @ W2  (ELU fused into A-load)
    {
        dim3 grid(OUT_C / 64, (N_NODES + 127) / 128);
        gemm_bf16x3<64, true><<<grid, 256>>>(pout1, pw2hi, pw2lo, ph2, N_NODES, OUT_C, F1);
    }
    // attention dots layer 2 (+ fp16 mirror)
    att2_kernel<<<(N_NODES + 255) / 256, 256>>>(att_src2, att_dst2);
    // GAT layer 2 -> embeddings (b2 folded, fp16 gathers)
    gat2_csr<<<(N_NODES + 7) / 8, 256>>>(emb, b2);
    // MLP head + softmax -> s
    mlp_kernel<<<(N_NODES + 63) / 64, 256>>>(emb, Wm1, bm1, Wm2, bm2, s_out);
}

// round 16
// speedup vs baseline: 1.2673x; 1.1547x over previous
#include <cuda_runtime.h>
#include <cuda_fp16.h>
#include <math.h>

#define N_NODES 50000
#define NUM_E   400000
#define ETOT    (NUM_E + N_NODES)   // 450000, self-loops appended
#define IN_C    128
#define HID     32
#define HEADS   8
#define F1      (HEADS * HID)       // 256
#define OUT_C   64
#define K_CL    16
#define NEG_SLOPE 0.2f
#define EPS_F   1e-16f

// ---------------- scratch (device globals; no runtime allocation) -----------
__device__ __half2 g_h1h[(size_t)N_NODES * (F1 / 2)];    // fp16 h1 (GEMM1 out)
__device__ float g_out1[(size_t)N_NODES * F1];   // layer1 output (incl. b1)
__device__ __half2 g_h2h[(size_t)N_NODES * (OUT_C / 2)]; // fp16 h2 (GEMM2 out)
__device__ float g_asrc1[N_NODES * HEADS];
__device__ float g_adst1[N_NODES * HEADS];
__device__ float g_asrc2[N_NODES];
__device__ float g_adst2[N_NODES];
// CSR by destination
__device__ int g_deg[N_NODES];
__device__ int g_start[N_NODES + 1];
__device__ int g_cursor[N_NODES];
__device__ int g_csr_src[ETOT];
__device__ int g_bsum[256];
// pre-split weights (packed bf16x2 along k-pairs): [K/2][N]
__device__ unsigned g_w1hi[(IN_C / 2) * F1];
__device__ unsigned g_w1lo[(IN_C / 2) * F1];
__device__ unsigned g_w2hi[(F1 / 2) * OUT_C];
__device__ unsigned g_w2lo[(F1 / 2) * OUT_C];

// ---------------- helpers ----------------------------------------------------
__device__ __forceinline__ float lrelu(float x) { return x > 0.f ? x : NEG_SLOPE * x; }
__device__ __forceinline__ float elu1(float x)  { return x > 0.f ? x : expm1f(x); }

__device__ __forceinline__ unsigned pack_bf16(float f_even, float f_odd) {
    unsigned r;
    asm("cvt.rn.satfinite.bf16x2.f32 %0, %1, %2;" : "=r"(r) : "f"(f_odd), "f"(f_even));
    return r;
}
__device__ __forceinline__ void bf16_split(float f0, float f1, unsigned& hi, unsigned& lo) {
    hi = pack_bf16(f0, f1);
    float b0 = __uint_as_float(hi << 16);
    float b1 = __uint_as_float(hi & 0xffff0000u);
    lo = pack_bf16(f0 - b0, f1 - b1);
}

#define MMA_BF16(d, a, b0_, b1_) \
    asm("mma.sync.aligned.m16n8k16.row.col.f32.bf16.bf16.f32 " \
        "{%0,%1,%2,%3}, {%4,%5,%6,%7}, {%8,%9}, {%0,%1,%2,%3};" \
        : "+f"(d[0]), "+f"(d[1]), "+f"(d[2]), "+f"(d[3]) \
        : "r"(a[0]), "r"(a[1]), "r"(a[2]), "r"(a[3]), "r"(b0_), "r"(b1_))

// ---------------- split both weight matrices (main stream) -------------------
__global__ void splitw_kernel(const float* __restrict__ W1, const float* __restrict__ W2) {
    int b = blockIdx.x, tid = threadIdx.x;
    if (b < 64) {                             // W1: (IN_C/2)*F1 = 16384 = 64*256
        int i = b * 256 + tid;
        int kp = i >> 8, n = i & 255;
        unsigned h, l;
        bf16_split(W1[(size_t)(2 * kp) * F1 + n], W1[(size_t)(2 * kp + 1) * F1 + n], h, l);
        g_w1hi[i] = h; g_w1lo[i] = l;
    } else {                                  // W2: (F1/2)*OUT_C = 8192 = 32*256
        int i = (b - 64) * 256 + tid;
        int kp = i >> 6, n = i & 63;
        unsigned h, l;
        bf16_split(W2[(size_t)(2 * kp) * OUT_C + n], W2[(size_t)(2 * kp + 1) * OUT_C + n], h, l);
        g_w2hi[i] = h; g_w2lo[i] = l;
    }
}

// ---------------- zero degree histogram (side stream head) -------------------
__global__ void zero_deg_kernel() {
    int i = blockIdx.x * blockDim.x + threadIdx.x;
    if (i < N_NODES) g_deg[i] = 0;
}

// ---------------- edge histogram ---------------------------------------------
__global__ void hist_kernel(const int* __restrict__ ei) {
    int e = blockIdx.x * blockDim.x + threadIdx.x;
    if (e >= ETOT) return;
    int d = (e < NUM_E) ? ei[NUM_E + e] : e - NUM_E;
    atomicAdd(&g_deg[d], 1);
}

// ---------------- CSR: 3-kernel scan + scatter --------------------------------
__global__ void scan1_kernel() {
    __shared__ int sm[256];
    int tid = threadIdx.x;
    int i = blockIdx.x * 256 + tid;
    int v = (i < N_NODES) ? g_deg[i] : 0;
    sm[tid] = v;
    __syncthreads();
    #pragma unroll
    for (int off = 1; off < 256; off <<= 1) {
        int t = (tid >= off) ? sm[tid - off] : 0;
        __syncthreads();
        sm[tid] += t;
        __syncthreads();
    }
    if (i < N_NODES) g_start[i] = sm[tid] - v;   // exclusive
    if (tid == 255) g_bsum[blockIdx.x] = sm[255];
}
__global__ void scan2_kernel(int nblocks) {
    __shared__ int sm[256];
    int tid = threadIdx.x;
    int v = (tid < nblocks) ? g_bsum[tid] : 0;
    sm[tid] = v;
    __syncthreads();
    #pragma unroll
    for (int off = 1; off < 256; off <<= 1) {
        int t = (tid >= off) ? sm[tid - off] : 0;
        __syncthreads();
        sm[tid] += t;
        __syncthreads();
    }
    if (tid < nblocks) g_bsum[tid] = sm[tid] - v;  // exclusive
}
__global__ void scan3_kernel() {
    int tid = threadIdx.x;
    int i = blockIdx.x * 256 + tid;
    if (i < N_NODES) {
        int s = g_start[i] + g_bsum[blockIdx.x];
        g_start[i] = s;
        g_cursor[i] = s;
    }
    if (i == 0) g_start[N_NODES] = ETOT;
}
__global__ void scatter_kernel(const int* __restrict__ ei) {
    int e = blockIdx.x * blockDim.x + threadIdx.x;
    if (e >= ETOT) return;
    int s, d;
    if (e < NUM_E) { s = ei[e]; d = ei[NUM_E + e]; } else { s = d = e - NUM_E; }
    int pos = atomicAdd(&g_cursor[d], 1);
    g_csr_src[pos] = s;
}

// ---------------- bf16 3-product tensor GEMM, fp16 out + fused att dots ------
// ATT=1: per-head dots (heads = 32-col groups) -> asrcO/adstO [N, 8]
// ATT=2: full-row dots -> asrcO/adstO [N]
#define AS_STRIDE 20
template<int BN, bool ELU_A, int ATT>
__global__ __launch_bounds__(256, 2) void gemm_bf16x3(
    const float* __restrict__ A,
    const unsigned* __restrict__ Bhi, const unsigned* __restrict__ Blo,
    __half2* __restrict__ mir, int M, int Nc, int Kc,
    const float* __restrict__ attS, const float* __restrict__ attD,
    float* __restrict__ asrcO, float* __restrict__ adstO)
{
    constexpr int NATOM = BN / 16;
    constexpr int BS_STRIDE = BN + 8;
    constexpr int NBQ = BN / 64;
    __shared__ unsigned sAhi[128 * AS_STRIDE];
    __shared__ unsigned sAlo[128 * AS_STRIDE];
    __shared__ unsigned sBhi[16 * BS_STRIDE];
    __shared__ unsigned sBlo[16 * BS_STRIDE];
    __shared__ float sAtt[128][2][2];   // ATT==2 cross-warp combine (row, nhalf, S/D)

    const int tid = threadIdx.x;
    const int warp = tid >> 5, lane = tid & 31;
    const int g = lane >> 2, tig = lane & 3;
    const int rowA = blockIdx.y * 128, colB = blockIdx.x * BN;
    const int wm = (warp >> 1) * 32, wn = (warp & 1) * (BN / 2);

    float d[2][NATOM][4];
    #pragma unroll
    for (int i = 0; i < 2; i++)
        #pragma unroll
        for (int j = 0; j < NATOM; j++)
            #pragma unroll
            for (int q = 0; q < 4; q++) d[i][j][q] = 0.f;

    const int arow = tid >> 1;
    const int ak0  = (tid & 1) * 16;
    const bool arow_ok = (rowA + arow) < M;
    const float* Aptr = A + (size_t)(rowA + arow) * Kc + ak0;

    const int bkp = tid >> 4;
    const int bn0 = (tid & 15) * (BN / 16);
    unsigned* sh = sBhi + bkp * BS_STRIDE + bn0;
    unsigned* sl = sBlo + bkp * BS_STRIDE + bn0;

    const int KT = Kc / 32;

    // prologue: load tile 0 into registers
    float4 fc[4];
    int4 bhc[NBQ], blc[NBQ];
    #pragma unroll
    for (int q = 0; q < 4; q++)
        fc[q] = arow_ok ? *(const float4*)(Aptr + q * 4) : make_float4(0.f, 0.f, 0.f, 0.f);
    #pragma unroll
    for (int q = 0; q < NBQ; q++) {
        bhc[q] = ((const int4*)(Bhi + (size_t)bkp * Nc + colB + bn0))[q];
        blc[q] = ((const int4*)(Blo + (size_t)bkp * Nc + colB + bn0))[q];
    }

    for (int kt = 0; kt < KT; kt++) {
        {
            float4 f[4];
            #pragma unroll
            for (int q = 0; q < 4; q++) f[q] = fc[q];
            if (ELU_A) {
                #pragma unroll
                for (int q = 0; q < 4; q++) {
                    f[q].x = elu1(f[q].x); f[q].y = elu1(f[q].y);
                    f[q].z = elu1(f[q].z); f[q].w = elu1(f[q].w);
                }
            }
            unsigned* hp = sAhi + arow * AS_STRIDE + (ak0 >> 1);
            unsigned* lp = sAlo + arow * AS_STRIDE + (ak0 >> 1);
            #pragma unroll
            for (int q = 0; q < 4; q++) {
                unsigned h0, l0, h1, l1;
                bf16_split(f[q].x, f[q].y, h0, l0);
                bf16_split(f[q].z, f[q].w, h1, l1);
                hp[q * 2] = h0; hp[q * 2 + 1] = h1;
                lp[q * 2] = l0; lp[q * 2 + 1] = l1;
            }
            #pragma unroll
            for (int q = 0; q < NBQ; q++) {
                ((int4*)sh)[q] = bhc[q];
                ((int4*)sl)[q] = blc[q];
            }
        }
        __syncthreads();

        if (kt + 1 < KT) {
            #pragma unroll
            for (int q = 0; q < 4; q++)
                fc[q] = arow_ok ? *(const float4*)(Aptr + (kt + 1) * 32 + q * 4)
                                : make_float4(0.f, 0.f, 0.f, 0.f);
            #pragma unroll
            for (int q = 0; q < NBQ; q++) {
                bhc[q] = ((const int4*)(Bhi + (size_t)((kt + 1) * 16 + bkp) * Nc + colB + bn0))[q];
                blc[q] = ((const int4*)(Blo + (size_t)((kt + 1) * 16 + bkp) * Nc + colB + bn0))[q];
            }
        }

        #pragma unroll
        for (int s = 0; s < 2; s++) {
            const int kp = s * 8 + tig;
            unsigned ahi[2][4], alo[2][4];
            #pragma unroll
            for (int am = 0; am < 2; am++) {
                int m0 = wm + am * 16 + g;
                ahi[am][0] = sAhi[m0 * AS_STRIDE + kp];
                ahi[am][1] = sAhi[(m0 + 8) * AS_STRIDE + kp];
                ahi[am][2] = sAhi[m0 * AS_STRIDE + kp + 4];
                ahi[am][3] = sAhi[(m0 + 8) * AS_STRIDE + kp + 4];
                alo[am][0] = sAlo[m0 * AS_STRIDE + kp];
                alo[am][1] = sAlo[(m0 + 8) * AS_STRIDE + kp];
                alo[am][2] = sAlo[m0 * AS_STRIDE + kp + 4];
                alo[am][3] = sAlo[(m0 + 8) * AS_STRIDE + kp + 4];
            }
            #pragma unroll
            for (int an = 0; an < NATOM; an++) {
                int n = wn + an * 8 + g;
                unsigned bh0 = sBhi[kp * BS_STRIDE + n];
                unsigned bh1 = sBhi[(kp + 4) * BS_STRIDE + n];
                unsigned bl0 = sBlo[kp * BS_STRIDE + n];
                unsigned bl1 = sBlo[(kp + 4) * BS_STRIDE + n];
                #pragma unroll
                for (int am = 0; am < 2; am++) {
                    MMA_BF16(d[am][an], ahi[am], bh0, bh1);
                    MMA_BF16(d[am][an], alo[am], bh0, bh1);
                    MMA_BF16(d[am][an], ahi[am], bl0, bl1);
                }
            }
        }
        __syncthreads();
    }

    // ---- epilogue: fp16 mirror store (from accumulators) ----
    #pragma unroll
    for (int am = 0; am < 2; am++) {
        int r0 = rowA + wm + am * 16 + g;
        #pragma unroll
        for (int an = 0; an < NATOM; an++) {
            int c = colB + wn + an * 8 + 2 * tig;
            if (r0 < M)
                mir[(size_t)r0 * (Nc / 2) + (c >> 1)] =
                    __floats2half2_rn(d[am][an][0], d[am][an][1]);
            if (r0 + 8 < M)
                mir[(size_t)(r0 + 8) * (Nc / 2) + (c >> 1)] =
                    __floats2half2_rn(d[am][an][2], d[am][an][3]);
        }
    }

    // ---- epilogue: fused attention dots from accumulators ----
    if (ATT == 1) {
        float pS[2][2][2] = {}, pD[2][2][2] = {};
        #pragma unroll
        for (int am = 0; am < 2; am++)
            #pragma unroll
            for (int an = 0; an < NATOM; an++) {
                int hl = an >> 2;
                int c = colB + wn + an * 8 + 2 * tig;
                float s0 = attS[c], s1 = attS[c + 1];
                float t0 = attD[c], t1 = attD[c + 1];
                pS[am][0][hl] += d[am][an][0] * s0 + d[am][an][1] * s1;
                pS[am][1][hl] += d[am][an][2] * s0 + d[am][an][3] * s1;
                pD[am][0][hl] += d[am][an][0] * t0 + d[am][an][1] * t1;
                pD[am][1][hl] += d[am][an][2] * t0 + d[am][an][3] * t1;
            }
        #pragma unroll
        for (int am = 0; am < 2; am++)
            #pragma unroll
            for (int rh = 0; rh < 2; rh++)
                #pragma unroll
                for (int hl = 0; hl < 2; hl++) {
                    pS[am][rh][hl] += __shfl_xor_sync(0xffffffffu, pS[am][rh][hl], 1);
                    pS[am][rh][hl] += __shfl_xor_sync(0xffffffffu, pS[am][rh][hl], 2);
                    pD[am][rh][hl] += __shfl_xor_sync(0xffffffffu, pD[am][rh][hl], 1);
                    pD[am][rh][hl] += __shfl_xor_sync(0xffffffffu, pD[am][rh][hl], 2);
                }
        if (tig == 0) {
            int hbase = (colB + wn) >> 5;
            #pragma unroll
            for (int am = 0; am < 2; am++)
                #pragma unroll
                for (int rh = 0; rh < 2; rh++) {
                    int row = rowA + wm + am * 16 + rh * 8 + g;
                    if (row < M) {
                        #pragma unroll
                        for (int hl = 0; hl < 2; hl++) {
                            asrcO[row * 8 + hbase + hl] = pS[am][rh][hl];
                            adstO[row * 8 + hbase + hl] = pD[am][rh][hl];
                        }
                    }
                }
        }
    } else if (ATT == 2) {
        float pS[2][2] = {}, pD[2][2] = {};
        #pragma unroll
        for (int am = 0; am < 2; am++)
            #pragma unroll
            for (int an = 0; an < NATOM; an++) {
                int c = wn + an * 8 + 2 * tig;   // colB==0 for BN=64 single tile
                float s0 = attS[c], s1 = attS[c + 1];
                float t0 = attD[c], t1 = attD[c + 1];
                pS[am][0] += d[am][an][0] * s0 + d[am][an][1] * s1;
                pS[am][1] += d[am][an][2] * s0 + d[am][an][3] * s1;
                pD[am][0] += d[am][an][0] * t0 + d[am][an][1] * t1;
                pD[am][1] += d[am][an][2] * t0 + d[am][an][3] * t1;
            }
        #pragma unroll
        for (int am = 0; am < 2; am++)
            #pragma unroll
            for (int rh = 0; rh < 2; rh++) {
                pS[am][rh] += __shfl_xor_sync(0xffffffffu, pS[am][rh], 1);
                pS[am][rh] += __shfl_xor_sync(0xffffffffu, pS[am][rh], 2);
                pD[am][rh] += __shfl_xor_sync(0xffffffffu, pD[am][rh], 1);
                pD[am][rh] += __shfl_xor_sync(0xffffffffu, pD[am][rh], 2);
            }
        if (tig == 0) {
            #pragma unroll
            for (int am = 0; am < 2; am++)
                #pragma unroll
                for (int rh = 0; rh < 2; rh++) {
                    int rt = wm + am * 16 + rh * 8 + g;
                    sAtt[rt][warp & 1][0] = pS[am][rh];
                    sAtt[rt][warp & 1][1] = pD[am][rh];
                }
        }
        __syncthreads();
        if (tid < 128) {
            int row = rowA + tid;
            if (row < M) asrcO[row] = sAtt[tid][0][0] + sAtt[tid][1][0];
        } else {
            int row = rowA + tid - 128;
            if (row < M) adstO[row] = sAtt[tid - 128][0][1] + sAtt[tid - 128][1][1];
        }
    }
}

// ---------------- GAT layer 1: two-pass, fp16 gathers -------------------------
__global__ __launch_bounds__(256) void gat1_csr(const float* __restrict__ b1) {
    int warp = threadIdx.x >> 5, lane = threadIdx.x & 31;
    int n = blockIdx.x * 8 + warp;
    if (n >= N_NODES) return;
    int beg = g_start[n], end = g_start[n + 1];

    // pass 1: denominators for 8 heads; lane = (edge_group:2 | head:3)
    int h8 = lane & 7;
    int eg = lane >> 3;
    float adst_p1 = g_adst1[n * 8 + h8];
    float den = 0.f;
    for (int e0 = beg; e0 < end; e0 += 4) {
        int e = e0 + eg;
        if (e < end) {
            int s = g_csr_src[e];
            den += __expf(lrelu(g_asrc1[s * 8 + h8] + adst_p1));
        }
    }
    den += __shfl_xor_sync(0xffffffffu, den, 8);
    den += __shfl_xor_sync(0xffffffffu, den, 16);
    int head = lane >> 2;
    float inv = 1.f / (__shfl_sync(0xffffffffu, den, head) + EPS_F);
    float adst_h = g_adst1[n * 8 + head];

    // pass 2: accumulate alpha * h1[src] (fp16 gathers, 16 B/lane/edge)
    float4 a0 = ((const float4*)b1)[lane * 2];
    float4 a1 = ((const float4*)b1)[lane * 2 + 1];
    #pragma unroll 4
    for (int e = beg; e < end; e++) {
        int s = g_csr_src[e];
        float alpha = __expf(lrelu(g_asrc1[s * 8 + head] + adst_h)) * inv;
        uint4 raw = *(const uint4*)(g_h1h + (size_t)s * (F1 / 2) + lane * 4);
        float2 f0 = __half22float2(*reinterpret_cast<__half2*>(&raw.x));
        float2 f1 = __half22float2(*reinterpret_cast<__half2*>(&raw.y));
        float2 f2 = __half22float2(*reinterpret_cast<__half2*>(&raw.z));
        float2 f3 = __half22float2(*reinterpret_cast<__half2*>(&raw.w));
        a0.x += alpha * f0.x; a0.y += alpha * f0.y;
        a0.z += alpha * f1.x; a0.w += alpha * f1.y;
        a1.x += alpha * f2.x; a1.y += alpha * f2.y;
        a1.z += alpha * f3.x; a1.w += alpha * f3.y;
    }
    float4* op = (float4*)(g_out1 + (size_t)n * F1) + lane * 2;
    op[0] = a0; op[1] = a1;
}

// ---------------- GAT layer 2: two-pass, fp16 gathers -------------------------
__global__ __launch_bounds__(256) void gat2_csr(float* __restrict__ emb, const float* __restrict__ b2) {
    int warp = threadIdx.x >> 5, lane = threadIdx.x & 31;
    int n = blockIdx.x * 8 + warp;
    if (n >= N_NODES) return;
    int beg = g_start[n], end = g_start[n + 1];
    float adst = g_adst2[n];

    float den = 0.f;
    for (int e = beg + lane; e < end; e += 32)
        den += __expf(lrelu(g_asrc2[g_csr_src[e]] + adst));
    #pragma unroll
    for (int m = 16; m >= 1; m >>= 1) den += __shfl_xor_sync(0xffffffffu, den, m);
    float inv = 1.f / (den + EPS_F);

    float2 acc = *(const float2*)(b2 + lane * 2);
    #pragma unroll 4
    for (int e = beg; e < end; e++) {
        int s = g_csr_src[e];
        float alpha = __expf(lrelu(g_asrc2[s] + adst)) * inv;
        float2 v = __half22float2(g_h2h[(size_t)s * (OUT_C / 2) + lane]);
        acc.x += alpha * v.x;
        acc.y += alpha * v.y;
    }
    *(float2*)(emb + (size_t)n * OUT_C + lane * 2) = acc;
}

// ---------------- fused MLP head + softmax (64 nodes/block) ------------------
__global__ __launch_bounds__(256) void mlp_kernel(
    const float* __restrict__ emb,
    const float* __restrict__ Wm1, const float* __restrict__ bm1,
    const float* __restrict__ Wm2, const float* __restrict__ bm2,
    float* __restrict__ s_out)
{
    __shared__ float sW1[OUT_C * 128];   // 32 KB
    __shared__ float sW2[128 * K_CL];    // 8 KB
    __shared__ float sb1[128];
    __shared__ float sb2[K_CL];
    __shared__ float sHid[8][128];
    __shared__ float sEmb[8][OUT_C];
    int tid = threadIdx.x;
    for (int i = tid; i < OUT_C * 128; i += 256) sW1[i] = Wm1[i];
    for (int i = tid; i < 128 * K_CL; i += 256) sW2[i] = Wm2[i];
    if (tid < 128) sb1[tid] = bm1[tid];
    if (tid < K_CL) sb2[tid] = bm2[tid];
    __syncthreads();
    int warp = tid >> 5, lane = tid & 31;
    #pragma unroll
    for (int it = 0; it < 8; it++) {
        int n = blockIdx.x * 64 + it * 8 + warp;
        if (n >= N_NODES) continue;
        float2 e2 = *(const float2*)(emb + (size_t)n * OUT_C + lane * 2);
        sEmb[warp][lane * 2] = e2.x;
        sEmb[warp][lane * 2 + 1] = e2.y;
        __syncwarp();
        #pragma unroll
        for (int w = 0; w < 4; w++) {
            int j = lane + w * 32;
            float acc = sb1[j];
            #pragma unroll 8
            for (int c = 0; c < OUT_C; c++) acc += sEmb[warp][c] * sW1[c * 128 + j];
            sHid[warp][j] = fmaxf(acc, 0.f);
        }
        __syncwarp();
        if (lane < K_CL) {
            float lg = sb2[lane];
            #pragma unroll 16
            for (int k = 0; k < 128; k++) lg += sHid[warp][k] * sW2[k * K_CL + lane];
            float mx = lg;
            #pragma unroll
            for (int m = 8; m >= 1; m >>= 1)
                mx = fmaxf(mx, __shfl_xor_sync(0xffff, mx, m, 16));
            float ev = __expf(lg - mx);
            float sum = ev;
            #pragma unroll
            for (int m = 8; m >= 1; m >>= 1)
                sum += __shfl_xor_sync(0xffff, sum, m, 16);
            s_out[(size_t)n * K_CL + lane] = ev / sum;
        }
        __syncwarp();
    }
}

// ---------------- side-stream handles (created once; same work every call) ---
static cudaStream_t side_stream() {
    static cudaStream_t s = [] {
        cudaStream_t t;
        cudaStreamCreateWithFlags(&t, cudaStreamNonBlocking);
        return t;
    }();
    return s;
}
static cudaEvent_t fork_event() {
    static cudaEvent_t e = [] {
        cudaEvent_t t;
        cudaEventCreateWithFlags(&t, cudaEventDisableTiming);
        return t;
    }();
    return e;
}
static cudaEvent_t join_event() {
    static cudaEvent_t e = [] {
        cudaEvent_t t;
        cudaEventCreateWithFlags(&t, cudaEventDisableTiming);
        return t;
    }();
    return e;
}

// ---------------- launch ------------------------------------------------------
extern "C" void kernel_launch(void* const* d_in, const int* in_sizes, int n_in,
                              void* d_out, int out_size) {
    const float* x        = (const float*)d_in[0];
    const int*   ei       = (const int*)d_in[1];     // [2, E]: src then dst
    const float* W1       = (const float*)d_in[2];
    const float* att_src1 = (const float*)d_in[3];
    const float* att_dst1 = (const float*)d_in[4];
    const float* b1       = (const float*)d_in[5];
    const float* W2       = (const float*)d_in[6];
    const float* att_src2 = (const float*)d_in[7];
    const float* att_dst2 = (const float*)d_in[8];
    const float* b2       = (const float*)d_in[9];
    const float* Wm1      = (const float*)d_in[10];
    const float* bm1      = (const float*)d_in[11];
    const float* Wm2      = (const float*)d_in[12];
    const float* bm2      = (const float*)d_in[13];

    float* s_out = (float*)d_out;                           // [N, 16]
    float* emb   = (float*)d_out + (size_t)N_NODES * K_CL;  // [N, 64]

    float *pout1, *pasrc1, *padst1, *pasrc2, *padst2;
    __half2 *ph1h, *ph2h;
    cudaGetSymbolAddress((void**)&pout1, g_out1);
    cudaGetSymbolAddress((void**)&ph1h, g_h1h);
    cudaGetSymbolAddress((void**)&ph2h, g_h2h);
    cudaGetSymbolAddress((void**)&pasrc1, g_asrc1);
    cudaGetSymbolAddress((void**)&padst1, g_adst1);
    cudaGetSymbolAddress((void**)&pasrc2, g_asrc2);
    cudaGetSymbolAddress((void**)&padst2, g_adst2);
    unsigned *pw1hi, *pw1lo, *pw2hi, *pw2lo;
    cudaGetSymbolAddress((void**)&pw1hi, g_w1hi);
    cudaGetSymbolAddress((void**)&pw1lo, g_w1lo);
    cudaGetSymbolAddress((void**)&pw2hi, g_w2hi);
    cudaGetSymbolAddress((void**)&pw2lo, g_w2lo);

    const int NSCAN = (N_NODES + 255) / 256;   // 196
    cudaStream_t s2 = side_stream();
    cudaEvent_t evF = fork_event(), evJ = join_event();

    // fork immediately: CSR chain on side stream, GEMM path on main stream
    cudaEventRecord(evF, 0);
    cudaStreamWaitEvent(s2, evF, 0);

    // side stream: zero deg -> hist -> scan -> scatter
    zero_deg_kernel<<<NSCAN, 256, 0, s2>>>();
    hist_kernel<<<(ETOT + 255) / 256, 256, 0, s2>>>(ei);
    scan1_kernel<<<NSCAN, 256, 0, s2>>>();
    scan2_kernel<<<1, 256, 0, s2>>>(NSCAN);
    scan3_kernel<<<NSCAN, 256, 0, s2>>>();
    scatter_kernel<<<(ETOT + 255) / 256, 256, 0, s2>>>(ei);

    // main stream: weight splits -> GEMM1 (fp16 out + att1 dots fused)
    splitw_kernel<<<96, 256>>>(W1, W2);
    {
        dim3 grid(F1 / 128, (N_NODES + 127) / 128);
        gemm_bf16x3<128, false, 1><<<grid, 256>>>(
            x, pw1hi, pw1lo, ph1h, N_NODES, F1, IN_C,
            att_src1, att_dst1, pasrc1, padst1);
    }

    // join: gat1 needs both CSR (s2) and GEMM1 outputs (main)
    cudaEventRecord(evJ, s2);
    cudaStreamWaitEvent(0, evJ, 0);

    // GAT layer 1 (b1 folded, fp16 gathers)
    gat1_csr<<<(N_NODES + 7) / 8, 256>>>(b1);
    // GEMM2: h2h = fp16(ELU(out1) @ W2) + att2 dots fused
    {
        dim3 grid(OUT_C / 64, (N_NODES + 127) / 128);
        gemm_bf16x3<64, true, 2><<<grid, 256>>>(
            pout1, pw2hi, pw2lo, ph2h, N_NODES, OUT_C, F1,
            att_src2, att_dst2, pasrc2, padst2);
    }
    // GAT layer 2 -> embeddings (b2 folded, fp16 gathers)
    gat2_csr<<<(N_NODES + 7) / 8, 256>>>(emb, b2);
    // MLP head + softmax -> s
    mlp_kernel<<<(N_NODES + 63) / 64, 256>>>(emb, Wm1, bm1, Wm2, bm2, s_out);
}